// round 14
// baseline (speedup 1.0000x reference)
#include <cuda_runtime.h>
#include <cuda_bf16.h>
#include <math.h>
#include <stdint.h>

#define Bsz 262144
#define IN_D 54
#define HID 256
#define EXPD 512
#define LAT 32
#define NB 4
#define NC 512
#define EPSL 1e-5f

// ---------------- scratch (device globals: allocation-free) ----------------
__device__ float g_h [(size_t)Bsz * HID];
__device__ float g_hn[(size_t)Bsz * HID];
__device__ float g_y [(size_t)Bsz * EXPD];
__device__ float g_z [(size_t)Bsz * LAT];
__device__ float g_zq[(size_t)Bsz * LAT];
__device__ float g_part[Bsz / 32];
__device__ float g_stats[(size_t)Bsz * 2];
__device__ __nv_bfloat16 g_wh16[1048576];
__device__ __nv_bfloat16 g_wl16[1048576];
__device__ __nv_bfloat16 g_ah16[(size_t)Bsz * HID];
__device__ __nv_bfloat16 g_al16[(size_t)Bsz * HID];

// ---------------- helpers ----------------
__device__ __forceinline__ uint32_t smem_u32(const void* p) {
    uint32_t a;
    asm("{ .reg .u64 t; cvta.to.shared.u64 t, %1; cvt.u32.u64 %0, t; }" : "=r"(a) : "l"(p));
    return a;
}
__device__ __forceinline__ float gelu_erf(float v) {
    return 0.5f * v * (1.0f + erff(v * 0.70710678118654752f));
}
__device__ __forceinline__ void mma_bf16(float* c, const uint32_t* a, const uint32_t* b) {
    asm volatile(
        "mma.sync.aligned.m16n8k16.row.col.f32.bf16.bf16.f32 "
        "{%0,%1,%2,%3}, {%4,%5,%6,%7}, {%8,%9}, {%0,%1,%2,%3};"
        : "+f"(c[0]), "+f"(c[1]), "+f"(c[2]), "+f"(c[3])
        : "r"(a[0]), "r"(a[1]), "r"(a[2]), "r"(a[3]), "r"(b[0]), "r"(b[1]));
}
__device__ __forceinline__ void bsplit2(float vx, float vy, uint32_t& hw, uint32_t& lw) {
    __nv_bfloat16 hx = __float2bfloat16(vx);
    __nv_bfloat16 hy = __float2bfloat16(vy);
    __nv_bfloat16 lx = __float2bfloat16(vx - __bfloat162float(hx));
    __nv_bfloat16 ly = __float2bfloat16(vy - __bfloat162float(hy));
    __nv_bfloat162 hp; hp.x = hx; hp.y = hy;
    __nv_bfloat162 lp; lp.x = lx; lp.y = ly;
    hw = *(uint32_t*)&hp;
    lw = *(uint32_t*)&lp;
}

#define FFMA2(accp, ap, bp) \
    asm volatile("fma.rn.f32x2 %0, %1, %2, %0;" : "+l"(accp) : "l"(ap), "l"(bp))
#define PACK_DUP(dst, s) \
    asm("mov.b64 %0, {%1, %1};" : "=l"(dst) : "f"(s))
#define UNPACK2(lo, hi, src) \
    asm("mov.b64 {%0, %1}, %2;" : "=f"(lo), "=f"(hi) : "l"(src))

#define CP16(dst, src) \
    asm volatile("cp.async.cg.shared.global [%0], [%1], 16;" :: "r"(dst), "l"(src) : "memory")
#define CP_COMMIT() asm volatile("cp.async.commit_group;" ::: "memory")
#define CP_WAIT0()  asm volatile("cp.async.wait_group 0;" ::: "memory")
#define CP_WAIT1()  asm volatile("cp.async.wait_group 1;" ::: "memory")

#define LDSM_X4(r0, r1, r2, r3, addr) \
    asm volatile("ldmatrix.sync.aligned.m8n8.x4.shared.b16 {%0,%1,%2,%3}, [%4];" \
        : "=r"(r0), "=r"(r1), "=r"(r2), "=r"(r3) : "r"(addr))
#define LDSM_X2(r0, r1, addr) \
    asm volatile("ldmatrix.sync.aligned.m8n8.x2.shared.b16 {%0,%1}, [%2];" \
        : "=r"(r0), "=r"(r1) : "r"(addr))

#define AKEY(k) (((((k) & 12) >> 2)) | (((k) & 3) << 2))
#define BPRM(s) ((s) ^ (((s) >> 3) & 1))

// ============================================================================
// ENCODER fp32 GEMM — FFMA2 with pre-duplicated A pairs in SMEM.
// FFMA2 operand values identical to round 13 (duplication moved to fill).
// ============================================================================
__global__ __launch_bounds__(256, 2)
void gemm128(const float* __restrict__ A, const float* __restrict__ W,
             const float* __restrict__ bias, const float* __restrict__ res,
             float* __restrict__ C, int K, int N, int epi,
             const float2* __restrict__ stats,
             const float* __restrict__ lng, const float* __restrict__ lnb)
{
    __shared__ __align__(16) unsigned long long As[2][2048];  // pairs (a,a)
    __shared__ __align__(16) float Ws[2][2048];

    const int tid = threadIdx.x;
    const int tx = tid & 15, ty = tid >> 4;
    const size_t row0 = (size_t)blockIdx.y * 128;
    const int col0 = blockIdx.x * 128;

    const int ar0 = tid >> 2, ar1 = ar0 + 64;
    const int ac  = (tid & 3) * 4;
    const int wr0 = tid >> 5, wr1 = wr0 + 8;
    const int ws  = tid & 31;
    const int wsw = BPRM(ws) * 4;
    const int wc  = ws * 4;

    const uint32_t wbase = smem_u32(Ws);

    float2 st0, st1;
    if (stats) {
        st0 = __ldg(stats + row0 + ar0);
        st1 = __ldg(stats + row0 + ar1);
    }

    unsigned long long acc2[8][4];
#pragma unroll
    for (int i = 0; i < 8; i++)
#pragma unroll
        for (int j = 0; j < 4; j++) acc2[i][j] = 0ULL;

    const int bo0 = BPRM(tx * 2) * 4;
    const int bo1 = BPRM(tx * 2 + 1) * 4;

    const int nch = K >> 4;
    float4 av0, av1;

    CP16(wbase + (uint32_t)(0 * 2048 + wr0 * 128 + wsw) * 4, W + (size_t)wr0 * N + col0 + wc);
    CP16(wbase + (uint32_t)(0 * 2048 + wr1 * 128 + wsw) * 4, W + (size_t)wr1 * N + col0 + wc);
    CP_COMMIT();
    av0 = *(const float4*)(A + (row0 + ar0) * K + ac);
    av1 = *(const float4*)(A + (row0 + ar1) * K + ac);
    if (stats) {
        av0.x = fmaf((av0.x - st0.x) * st0.y, __ldg(lng + ac + 0), __ldg(lnb + ac + 0));
        av0.y = fmaf((av0.y - st0.x) * st0.y, __ldg(lng + ac + 1), __ldg(lnb + ac + 1));
        av0.z = fmaf((av0.z - st0.x) * st0.y, __ldg(lng + ac + 2), __ldg(lnb + ac + 2));
        av0.w = fmaf((av0.w - st0.x) * st0.y, __ldg(lng + ac + 3), __ldg(lnb + ac + 3));
        av1.x = fmaf((av1.x - st1.x) * st1.y, __ldg(lng + ac + 0), __ldg(lnb + ac + 0));
        av1.y = fmaf((av1.y - st1.x) * st1.y, __ldg(lng + ac + 1), __ldg(lnb + ac + 1));
        av1.z = fmaf((av1.z - st1.x) * st1.y, __ldg(lng + ac + 2), __ldg(lnb + ac + 2));
        av1.w = fmaf((av1.w - st1.x) * st1.y, __ldg(lng + ac + 3), __ldg(lnb + ac + 3));
    }
    {
        float v0[4] = {av0.x, av0.y, av0.z, av0.w};
        float v1[4] = {av1.x, av1.y, av1.z, av1.w};
#pragma unroll
        for (int j = 0; j < 4; j++) {
            int kidx = ac + j;
            unsigned long long d0, d1;
            PACK_DUP(d0, v0[j]);
            PACK_DUP(d1, v1[j]);
            As[0][kidx * 128 + ((((ar0 >> 2) ^ AKEY(kidx)) << 2) | (ar0 & 3))] = d0;
            As[0][kidx * 128 + ((((ar1 >> 2) ^ AKEY(kidx)) << 2) | (ar1 & 3))] = d1;
        }
    }
    CP_WAIT0();
    __syncthreads();

    for (int c = 0; c < nch; c++) {
        const int buf = c & 1;
        if (c + 1 < nch) {
            const int kk = (c + 1) << 4;
            CP16(wbase + (uint32_t)((buf ^ 1) * 2048 + wr0 * 128 + wsw) * 4,
                 W + (size_t)(kk + wr0) * N + col0 + wc);
            CP16(wbase + (uint32_t)((buf ^ 1) * 2048 + wr1 * 128 + wsw) * 4,
                 W + (size_t)(kk + wr1) * N + col0 + wc);
            CP_COMMIT();
            av0 = *(const float4*)(A + (row0 + ar0) * K + kk + ac);
            av1 = *(const float4*)(A + (row0 + ar1) * K + kk + ac);
        }
#pragma unroll
        for (int k = 0; k < 16; k++) {
            unsigned long long a2[8];
            {
                const unsigned long long* p0 = &As[buf][k * 128 + (((ty * 2)     ^ AKEY(k)) << 2)];
                const unsigned long long* p1 = &As[buf][k * 128 + (((ty * 2 + 1) ^ AKEY(k)) << 2)];
                ulonglong2 q0 = *(const ulonglong2*)(p0);
                ulonglong2 q1 = *(const ulonglong2*)(p0 + 2);
                ulonglong2 q2 = *(const ulonglong2*)(p1);
                ulonglong2 q3 = *(const ulonglong2*)(p1 + 2);
                a2[0] = q0.x; a2[1] = q0.y; a2[2] = q1.x; a2[3] = q1.y;
                a2[4] = q2.x; a2[5] = q2.y; a2[6] = q3.x; a2[7] = q3.y;
            }
            ulonglong2 vb0 = *(const ulonglong2*)&Ws[buf][k * 128 + bo0];
            ulonglong2 vb1 = *(const ulonglong2*)&Ws[buf][k * 128 + bo1];
            unsigned long long b2[4] = {vb0.x, vb0.y, vb1.x, vb1.y};
#pragma unroll
            for (int i = 0; i < 8; i++)
#pragma unroll
                for (int j = 0; j < 4; j++)
                    FFMA2(acc2[i][j], a2[i], b2[j]);
        }
        if (c + 1 < nch) {
            const int kk = (c + 1) << 4;
            if (stats) {
                av0.x = fmaf((av0.x - st0.x) * st0.y, __ldg(lng + kk + ac + 0), __ldg(lnb + kk + ac + 0));
                av0.y = fmaf((av0.y - st0.x) * st0.y, __ldg(lng + kk + ac + 1), __ldg(lnb + kk + ac + 1));
                av0.z = fmaf((av0.z - st0.x) * st0.y, __ldg(lng + kk + ac + 2), __ldg(lnb + kk + ac + 2));
                av0.w = fmaf((av0.w - st0.x) * st0.y, __ldg(lng + kk + ac + 3), __ldg(lnb + kk + ac + 3));
                av1.x = fmaf((av1.x - st1.x) * st1.y, __ldg(lng + kk + ac + 0), __ldg(lnb + kk + ac + 0));
                av1.y = fmaf((av1.y - st1.x) * st1.y, __ldg(lng + kk + ac + 1), __ldg(lnb + kk + ac + 1));
                av1.z = fmaf((av1.z - st1.x) * st1.y, __ldg(lng + kk + ac + 2), __ldg(lnb + kk + ac + 2));
                av1.w = fmaf((av1.w - st1.x) * st1.y, __ldg(lng + kk + ac + 3), __ldg(lnb + kk + ac + 3));
            }
            float v0[4] = {av0.x, av0.y, av0.z, av0.w};
            float v1[4] = {av1.x, av1.y, av1.z, av1.w};
#pragma unroll
            for (int j = 0; j < 4; j++) {
                int kidx = ac + j;
                unsigned long long d0, d1;
                PACK_DUP(d0, v0[j]);
                PACK_DUP(d1, v1[j]);
                As[buf ^ 1][kidx * 128 + ((((ar0 >> 2) ^ AKEY(kidx)) << 2) | (ar0 & 3))] = d0;
                As[buf ^ 1][kidx * 128 + ((((ar1 >> 2) ^ AKEY(kidx)) << 2) | (ar1 & 3))] = d1;
            }
            CP_WAIT0();
        }
        __syncthreads();
    }

    // ---- epilogue: identical values, float2 I/O ----
#pragma unroll
    for (int i = 0; i < 8; i++) {
        size_t r = row0 + ty * 8 + i;
#pragma unroll
        for (int jc = 0; jc < 4; jc++) {
            float e0, e1;
            UNPACK2(e0, e1, acc2[i][jc]);
            int cix = col0 + tx * 8 + jc * 2;
            float2 bv = __ldg((const float2*)(bias + cix));
            float v0 = e0 + bv.x;
            float v1 = e1 + bv.y;
            if (epi == 1) {
                v0 = 0.5f * v0 * (1.0f + erff(v0 * 0.70710678118654752f));
                v1 = 0.5f * v1 * (1.0f + erff(v1 * 0.70710678118654752f));
            } else if (epi == 2) {
                float2 rv = *(const float2*)(res + r * N + cix);
                v0 += rv.x;
                v1 += rv.y;
            }
            *(float2*)(C + r * N + cix) = make_float2(v0, v1);
        }
    }
}

// ---------------- per-row layernorm stats (encoder) ----------------
__global__ void ln_stats(const float* __restrict__ H, float2* __restrict__ st)
{
    int gw = (int)((blockIdx.x * blockDim.x + threadIdx.x) >> 5);
    int lane = threadIdx.x & 31;
    const float* h = H + (size_t)gw * HID + lane * 8;
    float4 v0 = *(const float4*)h;
    float4 v1 = *(const float4*)(h + 4);
    float v[8] = {v0.x, v0.y, v0.z, v0.w, v1.x, v1.y, v1.z, v1.w};
    float s = 0.f;
#pragma unroll
    for (int k = 0; k < 8; k++) s += v[k];
#pragma unroll
    for (int o = 16; o; o >>= 1) s += __shfl_xor_sync(0xffffffffu, s, o);
    float mu = s * (1.0f / HID);
    float q = 0.f;
#pragma unroll
    for (int k = 0; k < 8; k++) { float d = v[k] - mu; q = fmaf(d, d, q); }
#pragma unroll
    for (int o = 16; o; o >>= 1) q += __shfl_xor_sync(0xffffffffu, q, o);
    float w = rsqrtf(q * (1.0f / HID) + EPSL);
    if (lane == 0) st[gw] = make_float2(mu, w);
}

// ---------------- full layernorm (final norms) ----------------
__global__ void ln_kernel(const float* __restrict__ H, const float* __restrict__ g,
                          const float* __restrict__ b, float* __restrict__ O)
{
    int gw = (int)((blockIdx.x * blockDim.x + threadIdx.x) >> 5);
    int lane = threadIdx.x & 31;
    const float* h = H + (size_t)gw * HID + lane * 8;
    float4 v0 = *(const float4*)h;
    float4 v1 = *(const float4*)(h + 4);
    float v[8] = {v0.x, v0.y, v0.z, v0.w, v1.x, v1.y, v1.z, v1.w};
    float s = 0.f;
#pragma unroll
    for (int k = 0; k < 8; k++) s += v[k];
#pragma unroll
    for (int o = 16; o; o >>= 1) s += __shfl_xor_sync(0xffffffffu, s, o);
    float mu = s * (1.0f / HID);
    float d[8], q = 0.f;
#pragma unroll
    for (int k = 0; k < 8; k++) { d[k] = v[k] - mu; q = fmaf(d[k], d[k], q); }
#pragma unroll
    for (int o = 16; o; o >>= 1) q += __shfl_xor_sync(0xffffffffu, q, o);
    float w = rsqrtf(q * (1.0f / HID) + EPSL);
    const float* gg = g + lane * 8;
    const float* bb = b + lane * 8;
    float o8[8];
#pragma unroll
    for (int k = 0; k < 8; k++) o8[k] = fmaf(d[k] * w, __ldg(gg + k), __ldg(bb + k));
    float* op = O + (size_t)gw * HID + lane * 8;
    *(float4*)op = make_float4(o8[0], o8[1], o8[2], o8[3]);
    *(float4*)(op + 4) = make_float4(o8[4], o8[5], o8[6], o8[7]);
}

// ---------------- layernorm + bf16 hi/lo split (decoder) ----------------
__global__ void ln_split(const float* __restrict__ H, const float* __restrict__ g,
                         const float* __restrict__ b,
                         __nv_bfloat16* __restrict__ Oh, __nv_bfloat16* __restrict__ Ol)
{
    int gw = (int)((blockIdx.x * blockDim.x + threadIdx.x) >> 5);
    int lane = threadIdx.x & 31;
    const float* h = H + (size_t)gw * HID + lane * 8;
    float4 v0 = *(const float4*)h;
    float4 v1 = *(const float4*)(h + 4);
    float v[8] = {v0.x, v0.y, v0.z, v0.w, v1.x, v1.y, v1.z, v1.w};
    float s = 0.f;
#pragma unroll
    for (int k = 0; k < 8; k++) s += v[k];
#pragma unroll
    for (int o = 16; o; o >>= 1) s += __shfl_xor_sync(0xffffffffu, s, o);
    float mu = s * (1.0f / HID);
    float d[8], q = 0.f;
#pragma unroll
    for (int k = 0; k < 8; k++) { d[k] = v[k] - mu; q = fmaf(d[k], d[k], q); }
#pragma unroll
    for (int o = 16; o; o >>= 1) q += __shfl_xor_sync(0xffffffffu, q, o);
    float w = rsqrtf(q * (1.0f / HID) + EPSL);
    const float* gg = g + lane * 8;
    const float* bb = b + lane * 8;
    uint32_t wh[4], wl[4];
#pragma unroll
    for (int p = 0; p < 4; p++) {
        float oa = fmaf(d[2 * p] * w, __ldg(gg + 2 * p), __ldg(bb + 2 * p));
        float ob = fmaf(d[2 * p + 1] * w, __ldg(gg + 2 * p + 1), __ldg(bb + 2 * p + 1));
        bsplit2(oa, ob, wh[p], wl[p]);
    }
    *(uint4*)(Oh + (size_t)gw * HID + lane * 8) = make_uint4(wh[0], wh[1], wh[2], wh[3]);
    *(uint4*)(Ol + (size_t)gw * HID + lane * 8) = make_uint4(wl[0], wl[1], wl[2], wl[3]);
}

// ---------------- small GEMMs (round-13, conflict-free, bit-exact) ---------
template <int K>
__global__ __launch_bounds__(256)
void small_gemm_n256(const float* __restrict__ A, const float* __restrict__ W,
                     const float* __restrict__ bias, float* __restrict__ C)
{
    extern __shared__ float smx[];
    float* sW = smx;
    float* sAT = smx + K * 256;
    const int tid = threadIdx.x;
    const size_t row0 = (size_t)blockIdx.x * 32;
    for (int i = tid; i < K * 256; i += 256) {
        int k = i >> 8, c = i & 255;
        sW[k * 256 + (c ^ ((c >> 5) << 2))] = W[i];
    }
    for (int i = tid; i < 32 * K; i += 256) {
        int r = i / K, k = i - r * K;
        sAT[k * 32 + r] = A[(row0 + r) * K + k];
    }
    __syncthreads();
    const int r = tid >> 3;
    const int qq = tid & 7;
    const int c0 = qq * 32;
    float acc[32];
#pragma unroll
    for (int t = 0; t < 32; t++) acc[t] = 0.f;
#pragma unroll
    for (int k = 0; k < K; k++) {
        float a = sAT[k * 32 + r];
        const float* wrow = sW + k * 256;
#pragma unroll
        for (int j = 0; j < 8; j++) {
            float4 w4 = *(const float4*)(wrow + ((c0 + 4 * j) ^ (qq << 2)));
            acc[4 * j + 0] = fmaf(a, w4.x, acc[4 * j + 0]);
            acc[4 * j + 1] = fmaf(a, w4.y, acc[4 * j + 1]);
            acc[4 * j + 2] = fmaf(a, w4.z, acc[4 * j + 2]);
            acc[4 * j + 3] = fmaf(a, w4.w, acc[4 * j + 3]);
        }
    }
    float* cp = C + (row0 + r) * 256 + c0;
#pragma unroll
    for (int t = 0; t < 32; t++) cp[t] = acc[t] + __ldg(bias + c0 + t);
}

__global__ __launch_bounds__(256)
void small_gemm_n32(const float* __restrict__ A, const float* __restrict__ W,
                    const float* __restrict__ bias, float* __restrict__ C)
{
    extern __shared__ float smx[];
    float* sW = smx;
    float* sAT = smx + 256 * 32;
    const int tid = threadIdx.x;
    const size_t row0 = (size_t)blockIdx.x * 32;
    for (int i = tid; i < 256 * 32; i += 256) sW[i] = W[i];
    for (int i = tid; i < 32 * 256; i += 256) {
        int r = i >> 8, k = i & 255;
        sAT[k * 32 + r] = A[(row0 + r) * 256 + k];
    }
    __syncthreads();
    const int r = tid >> 3;
    const int c0 = (tid & 7) * 4;
    float acc[4] = {0.f, 0.f, 0.f, 0.f};
#pragma unroll
    for (int k = 0; k < 256; k++) {
        float a = sAT[k * 32 + r];
        const float* wr = sW + k * 32 + c0;
#pragma unroll
        for (int t = 0; t < 4; t++) acc[t] = fmaf(a, wr[t], acc[t]);
    }
    float* cp = C + (row0 + r) * 32 + c0;
#pragma unroll
    for (int t = 0; t < 4; t++) cp[t] = acc[t] + __ldg(bias + c0 + t);
}

__global__ __launch_bounds__(256)
void small_gemm_n54(const float* __restrict__ A, const float* __restrict__ W,
                    const float* __restrict__ bias, float* __restrict__ C)
{
    extern __shared__ float smx[];
    float* sW = smx;
    float* sAT = smx + 256 * 54;
    const int tid = threadIdx.x;
    const size_t row0 = (size_t)blockIdx.x * 32;
    for (int i = tid; i < 256 * 54; i += 256) sW[i] = W[i];
    for (int i = tid; i < 32 * 256; i += 256) {
        int r = i >> 8, k = i & 255;
        sAT[k * 32 + r] = A[(row0 + r) * 256 + k];
    }
    __syncthreads();
    const int r = tid >> 3;
    const int c0 = (tid & 7) * 7;
    float acc[7] = {0.f, 0.f, 0.f, 0.f, 0.f, 0.f, 0.f};
#pragma unroll
    for (int k = 0; k < 256; k++) {
        float a = sAT[k * 32 + r];
        const float* wr = sW + k * 54 + c0;
#pragma unroll
        for (int t = 0; t < 7; t++)
            if (c0 + t < 54) acc[t] = fmaf(a, wr[t], acc[t]);
    }
    float* cp = C + (row0 + r) * 54 + c0;
#pragma unroll
    for (int t = 0; t < 7; t++)
        if (c0 + t < 54) cp[t] = acc[t] + __ldg(bias + c0 + t);
}

// ---------------- VQ: 4 rows per warp (round-13, bit-exact indices) --------
__global__ void vq_kernel(const float* __restrict__ Z, const float* __restrict__ CB,
                          float* __restrict__ idx_out, float* __restrict__ zq1,
                          float* __restrict__ zq2, float* __restrict__ part)
{
    extern __shared__ float smx[];
    float* scbT = smx;
    float* sn2 = smx + NC * LAT;
    __shared__ float swsum[8];
    int tid = threadIdx.x;
    for (int i = tid; i < NC * LAT; i += 256) {
        int c = i & (NC - 1);
        int j = i >> 9;
        scbT[j * NC + c] = CB[(size_t)c * LAT + j];
    }
    __syncthreads();
    for (int c = tid; c < NC; c += 256) {
        float s = 0.f;
#pragma unroll
        for (int j = 0; j < LAT; j++) { float t = scbT[j * NC + c]; s = fmaf(t, t, s); }
        sn2[c] = s;
    }
    __syncthreads();

    int warp = tid >> 5, lane = tid & 31;
    float wsum = 0.f;
#pragma unroll 1
    for (int rr4 = 0; rr4 < 4; rr4++) {
        size_t row = (size_t)blockIdx.x * 32 + warp * 4 + rr4;
        const float* z = Z + row * LAT;
        float zv[LAT];
#pragma unroll
        for (int j = 0; j < LAT; j++) zv[j] = z[j];

        float best = 3.4e38f;
        int bidx = 0;
        for (int c = lane; c < NC; c += 32) {
            float s = 0.f;
#pragma unroll
            for (int j = 0; j < LAT; j++) s = fmaf(zv[j], scbT[j * NC + c], s);
            float d2 = sn2[c] - 2.f * s;
            if (d2 < best) { best = d2; bidx = c; }
        }
#pragma unroll
        for (int o = 16; o; o >>= 1) {
            float ob = __shfl_xor_sync(0xffffffffu, best, o);
            int oi = __shfl_xor_sync(0xffffffffu, bidx, o);
            if (ob < best || (ob == best && oi < bidx)) { best = ob; bidx = oi; }
        }
        float zl = z[lane];
        float zq = scbT[lane * NC + bidx];
        float st = zl + (zq - zl);
        zq1[row * LAT + lane] = st;
        zq2[row * LAT + lane] = st;
        float df = zl - zq;
        float ps = df * df;
#pragma unroll
        for (int o = 16; o; o >>= 1) ps += __shfl_xor_sync(0xffffffffu, ps, o);
        if (lane == 0) {
            wsum += ps;
            idx_out[row] = (float)bidx;
        }
    }
    if (lane == 0) swsum[warp] = wsum;
    __syncthreads();
    if (tid == 0) {
        float t = 0.f;
        for (int wq = 0; wq < 8; wq++) t += swsum[wq];
        part[blockIdx.x] = t;
    }
}

__global__ void loss_reduce(const float* __restrict__ part, float* __restrict__ out)
{
    __shared__ float s[1024];
    int tid = threadIdx.x;
    float a = 0.f;
    for (int i = tid; i < Bsz / 32; i += 1024) a += part[i];
    s[tid] = a;
    __syncthreads();
    for (int o = 512; o; o >>= 1) {
        if (tid < o) s[tid] += s[tid + o];
        __syncthreads();
    }
    if (tid == 0) out[0] = s[0] / (float)((size_t)Bsz * LAT);
}

// ---------------- decoder weight prep ----------------
__global__ void tsplitT(const float* __restrict__ W, __nv_bfloat16* __restrict__ Th,
                        __nv_bfloat16* __restrict__ Tl, int K, int N)
{
    int i = blockIdx.x * 256 + threadIdx.x;
    if (i >= K * N) return;
    int n = i / K, k = i - n * K;
    float v = W[(size_t)k * N + n];
    __nv_bfloat16 hb = __float2bfloat16(v);
    Th[i] = hb;
    Tl[i] = __float2bfloat16(v - __bfloat162float(hb));
}

// ============================================================================
// DECODER GEMM — unchanged (at mma-pipe ceiling)
// ============================================================================
#define RST 20

__global__ __launch_bounds__(256, 2)
void mma2(const __nv_bfloat16* __restrict__ Ahg, const __nv_bfloat16* __restrict__ Alg,
          const __nv_bfloat16* __restrict__ Whg, const __nv_bfloat16* __restrict__ Wlg,
          const float* __restrict__ bias, const float* res, float* Cf,
          __nv_bfloat16* Yh, __nv_bfloat16* Yl, int K, int Ntot, int epi)
{
    extern __shared__ __align__(16) uint32_t dsm[];
    const uint32_t sbase = smem_u32(dsm);
    const int tid = threadIdx.x, lane = tid & 31, warp = tid >> 5;
    const int wm = warp >> 2, wn = warp & 3;
    const int q = lane & 3, rr = lane >> 2;
    const size_t row0 = (size_t)blockIdx.y * 128;
    const int n0 = blockIdx.x * 128;

    float acc[4][4][4];
#pragma unroll
    for (int a = 0; a < 4; a++)
#pragma unroll
        for (int b = 0; b < 4; b++)
#pragma unroll
            for (int c = 0; c < 4; c++) acc[a][b][c] = 0.f;

    uint32_t aoff[4], boff[4];
#pragma unroll
    for (int mt = 0; mt < 4; mt++)
        aoff[mt] = (uint32_t)((wm * 64 + mt * 16 + (lane & 15)) * (RST * 4) + (lane >> 4) * 16);
#pragma unroll
    for (int nt = 0; nt < 4; nt++)
        boff[nt] = (uint32_t)((wn * 32 + nt * 8 + (lane & 7)) * (RST * 4) + ((lane >> 3) & 1) * 16);

    auto fill = [&](int kc, int buf) {
        const uint32_t ah_b = sbase + (uint32_t)buf * 10240;
        const uint32_t al_b = sbase + 20480 + (uint32_t)buf * 10240;
        const uint32_t bh_b = sbase + 40960 + (uint32_t)buf * 10240;
        const uint32_t bl_b = sbase + 61440 + (uint32_t)buf * 10240;
#pragma unroll
        for (int i = 0; i < 4; i++) {
            int fid = tid + i * 256;
            int m = fid >> 3, c4 = fid & 3, lo = (fid >> 2) & 1;
            const __nv_bfloat16* s = (lo ? Alg : Ahg) + (row0 + m) * K + kc + c4 * 8;
            CP16((lo ? al_b : ah_b) + (uint32_t)(m * RST + c4 * 4) * 4, s);
        }
#pragma unroll
        for (int i = 0; i < 4; i++) {
            int fid = tid + i * 256;
            int m = fid >> 3, c4 = fid & 3, lo = (fid >> 2) & 1;
            const __nv_bfloat16* s = (lo ? Wlg : Whg) + (size_t)(n0 + m) * K + kc + c4 * 8;
            CP16((lo ? bl_b : bh_b) + (uint32_t)(m * RST + c4 * 4) * 4, s);
        }
    };

    const int nch = K >> 5;
    fill(0, 0);
    CP_COMMIT();
    for (int c = 0; c < nch; c++) {
        if (c + 1 < nch) {
            fill((c + 1) << 5, (c + 1) & 1);
            CP_COMMIT();
            CP_WAIT1();
        } else {
            CP_WAIT0();
        }
        __syncthreads();
        const int buf = c & 1;
        const uint32_t ah_b = sbase + (uint32_t)buf * 10240;
        const uint32_t al_b = sbase + 20480 + (uint32_t)buf * 10240;
        const uint32_t bh_b = sbase + 40960 + (uint32_t)buf * 10240;
        const uint32_t bl_b = sbase + 61440 + (uint32_t)buf * 10240;
#pragma unroll
        for (int ks = 0; ks < 2; ks++) {
            const uint32_t ko = (uint32_t)ks * 32;
            uint32_t ah[4][4], al[4][4], bh[4][2], bl[4][2];
#pragma unroll
            for (int mt = 0; mt < 4; mt++) {
                LDSM_X4(ah[mt][0], ah[mt][1], ah[mt][2], ah[mt][3], ah_b + aoff[mt] + ko);
                LDSM_X4(al[mt][0], al[mt][1], al[mt][2], al[mt][3], al_b + aoff[mt] + ko);
            }
#pragma unroll
            for (int nt = 0; nt < 4; nt++) {
                LDSM_X2(bh[nt][0], bh[nt][1], bh_b + boff[nt] + ko);
                LDSM_X2(bl[nt][0], bl[nt][1], bl_b + boff[nt] + ko);
            }
#pragma unroll
            for (int mt = 0; mt < 4; mt++)
#pragma unroll
                for (int nt = 0; nt < 4; nt++) {
                    mma_bf16(acc[mt][nt], ah[mt], bh[nt]);
                    mma_bf16(acc[mt][nt], ah[mt], bl[nt]);
                    mma_bf16(acc[mt][nt], al[mt], bh[nt]);
                }
        }
        __syncthreads();
    }

#pragma unroll
    for (int mt = 0; mt < 4; mt++) {
        size_t r0 = row0 + wm * 64 + mt * 16 + rr;
        size_t r1 = r0 + 8;
#pragma unroll
        for (int nt = 0; nt < 4; nt++) {
            int gc = n0 + wn * 32 + nt * 8 + q * 2;
            float2 bv = __ldg((const float2*)(bias + gc));
            float v00 = acc[mt][nt][0] + bv.x;
            float v01 = acc[mt][nt][1] + bv.y;
            float v10 = acc[mt][nt][2] + bv.x;
            float v11 = acc[mt][nt][3] + bv.y;
            if (epi == 1) {
                v00 = gelu_erf(v00); v01 = gelu_erf(v01);
                v10 = gelu_erf(v10); v11 = gelu_erf(v11);
                uint32_t h0, l0, h1, l1;
                bsplit2(v00, v01, h0, l0);
                bsplit2(v10, v11, h1, l1);
                *(uint32_t*)(Yh + r0 * Ntot + gc) = h0;
                *(uint32_t*)(Yl + r0 * Ntot + gc) = l0;
                *(uint32_t*)(Yh + r1 * Ntot + gc) = h1;
                *(uint32_t*)(Yl + r1 * Ntot + gc) = l1;
            } else {
                float2 rv0 = *(const float2*)(res + r0 * Ntot + gc);
                float2 rv1 = *(const float2*)(res + r1 * Ntot + gc);
                v00 += rv0.x; v01 += rv0.y; v10 += rv1.x; v11 += rv1.y;
                *(float2*)(Cf + r0 * Ntot + gc) = make_float2(v00, v01);
                *(float2*)(Cf + r1 * Ntot + gc) = make_float2(v10, v11);
            }
        }
    }
}

// ---------------- orchestration ----------------
extern "C" void kernel_launch(void* const* d_in, const int* in_sizes, int n_in,
                              void* d_out, int out_size)
{
    const float* x    = (const float*)d_in[0];
    const float* epw  = (const float*)d_in[1];
    const float* epb  = (const float*)d_in[2];
    const float* elng = (const float*)d_in[3];
    const float* elnb = (const float*)d_in[4];
    const float* ew1  = (const float*)d_in[5];
    const float* eb1  = (const float*)d_in[6];
    const float* ew2  = (const float*)d_in[7];
    const float* eb2  = (const float*)d_in[8];
    const float* eng  = (const float*)d_in[9];
    const float* enb  = (const float*)d_in[10];
    const float* elw  = (const float*)d_in[11];
    const float* elb  = (const float*)d_in[12];
    const float* cb   = (const float*)d_in[13];
    const float* dlw  = (const float*)d_in[14];
    const float* dlb  = (const float*)d_in[15];
    const float* dlng = (const float*)d_in[16];
    const float* dlnb = (const float*)d_in[17];
    const float* dw1  = (const float*)d_in[18];
    const float* db1  = (const float*)d_in[19];
    const float* dw2  = (const float*)d_in[20];
    const float* db2  = (const float*)d_in[21];
    const float* dng  = (const float*)d_in[22];
    const float* dnb  = (const float*)d_in[23];
    const float* dpw  = (const float*)d_in[24];
    const float* dpb  = (const float*)d_in[25];

    float* out = (float*)d_out;
    float* o_xrec = out;
    float* o_zq   = out + (size_t)Bsz * IN_D;
    float* o_idx  = o_zq + (size_t)Bsz * LAT;
    float* o_loss = o_idx + (size_t)Bsz;

    float *h, *hn, *y, *z, *zq, *part, *stats;
    __nv_bfloat16 *wh16, *wl16, *ah16, *al16;
    cudaGetSymbolAddress((void**)&h, g_h);
    cudaGetSymbolAddress((void**)&hn, g_hn);
    cudaGetSymbolAddress((void**)&y, g_y);
    cudaGetSymbolAddress((void**)&z, g_z);
    cudaGetSymbolAddress((void**)&zq, g_zq);
    cudaGetSymbolAddress((void**)&part, g_part);
    cudaGetSymbolAddress((void**)&stats, g_stats);
    cudaGetSymbolAddress((void**)&wh16, g_wh16);
    cudaGetSymbolAddress((void**)&wl16, g_wl16);
    cudaGetSymbolAddress((void**)&ah16, g_ah16);
    cudaGetSymbolAddress((void**)&al16, g_al16);

    __nv_bfloat16* yh16 = (__nv_bfloat16*)y;
    __nv_bfloat16* yl16 = yh16 + (size_t)Bsz * EXPD;

    const int MMA_SMEM = 81920;
    cudaFuncSetAttribute(mma2, cudaFuncAttributeMaxDynamicSharedMemorySize, MMA_SMEM);
    cudaFuncSetAttribute(vq_kernel, cudaFuncAttributeMaxDynamicSharedMemorySize, 70656);
    const int SM_N256_54 = (54 * 256 + 32 * 54) * 4;
    const int SM_N256_32 = (32 * 256 + 32 * 32) * 4;
    const int SM_N32     = (256 * 32 + 256 * 32) * 4;
    const int SM_N54     = (256 * 54 + 256 * 32) * 4;
    cudaFuncSetAttribute(small_gemm_n256<54>, cudaFuncAttributeMaxDynamicSharedMemorySize, SM_N256_54);
    cudaFuncSetAttribute(small_gemm_n256<32>, cudaFuncAttributeMaxDynamicSharedMemorySize, SM_N256_32);
    cudaFuncSetAttribute(small_gemm_n32, cudaFuncAttributeMaxDynamicSharedMemorySize, SM_N32);
    cudaFuncSetAttribute(small_gemm_n54, cudaFuncAttributeMaxDynamicSharedMemorySize, SM_N54);

    const size_t WSZ = 131072;
    const size_t OW1D = 0, OW2D = 4 * WSZ;

    // ---- encoder: frozen FFMA2 fp32 path (bit-identical z -> indices) ----
    small_gemm_n256<54><<<Bsz / 32, 256, SM_N256_54>>>(x, epw, epb, h);
    for (int i = 0; i < NB; i++) {
        ln_stats<<<Bsz / 8, 256>>>(h, (float2*)stats);
        gemm128<<<dim3(EXPD / 128, Bsz / 128), 256>>>(
            h, ew1 + (size_t)i * HID * EXPD, eb1 + i * EXPD, nullptr, y, HID, EXPD, 1,
            (const float2*)stats, elng + i * HID, elnb + i * HID);
        gemm128<<<dim3(HID / 128, Bsz / 128), 256>>>(
            y, ew2 + (size_t)i * EXPD * HID, eb2 + i * HID, h, h, EXPD, HID, 2,
            nullptr, nullptr, nullptr);
    }
    ln_kernel<<<Bsz / 8, 256>>>(h, eng, enb, hn);
    small_gemm_n32<<<Bsz / 32, 256, SM_N32>>>(hn, elw, elb, z);

    // ---- VQ ----
    vq_kernel<<<Bsz / 32, 256, (NC * LAT + NC) * 4>>>(z, cb, o_idx, o_zq, zq, part);
    loss_reduce<<<1, 1024>>>(part, o_loss);

    // ---- decoder weight prep ----
    for (int i = 0; i < NB; i++) {
        tsplitT<<<512, 256>>>(dw1 + i * WSZ, wh16 + OW1D + i * WSZ, wl16 + OW1D + i * WSZ, HID, EXPD);
        tsplitT<<<512, 256>>>(dw2 + i * WSZ, wh16 + OW2D + i * WSZ, wl16 + OW2D + i * WSZ, EXPD, HID);
    }

    // ---- decoder: bf16 split mma pipeline (unchanged) ----
    small_gemm_n256<32><<<Bsz / 32, 256, SM_N256_32>>>(zq, dlw, dlb, h);
    for (int i = 0; i < NB; i++) {
        ln_split<<<Bsz / 8, 256>>>(h, dlng + i * HID, dlnb + i * HID, ah16, al16);
        mma2<<<dim3(EXPD / 128, Bsz / 128), 256, MMA_SMEM>>>(
            ah16, al16, wh16 + OW1D + i * WSZ, wl16 + OW1D + i * WSZ, db1 + i * EXPD,
            nullptr, nullptr, yh16, yl16, HID, EXPD, 1);
        mma2<<<dim3(HID / 128, Bsz / 128), 256, MMA_SMEM>>>(
            yh16, yl16, wh16 + OW2D + i * WSZ, wl16 + OW2D + i * WSZ, db2 + i * HID,
            h, h, nullptr, nullptr, EXPD, HID, 2);
    }
    ln_kernel<<<Bsz / 8, 256>>>(h, dng, dnb, hn);
    small_gemm_n54<<<Bsz / 32, 256, SM_N54>>>(hn, dpw, dpb, o_xrec);
}

// round 15
// speedup vs baseline: 1.1102x; 1.1102x over previous
#include <cuda_runtime.h>
#include <cuda_bf16.h>
#include <math.h>
#include <stdint.h>

#define Bsz 262144
#define IN_D 54
#define HID 256
#define EXPD 512
#define LAT 32
#define NB 4
#define NC 512
#define EPSL 1e-5f

// ---------------- scratch (device globals: allocation-free) ----------------
__device__ float g_h [(size_t)Bsz * HID];
__device__ float g_hn[(size_t)Bsz * HID];
__device__ float g_y [(size_t)Bsz * EXPD];
__device__ float g_z [(size_t)Bsz * LAT];
__device__ float g_zq[(size_t)Bsz * LAT];
__device__ float g_part[Bsz / 32];
__device__ float g_stats[(size_t)Bsz * 2];
__device__ __nv_bfloat16 g_wh16[1048576];
__device__ __nv_bfloat16 g_wl16[1048576];
__device__ __nv_bfloat16 g_ah16[(size_t)Bsz * HID];
__device__ __nv_bfloat16 g_al16[(size_t)Bsz * HID];

// ---------------- helpers ----------------
__device__ __forceinline__ uint32_t smem_u32(const void* p) {
    uint32_t a;
    asm("{ .reg .u64 t; cvta.to.shared.u64 t, %1; cvt.u32.u64 %0, t; }" : "=r"(a) : "l"(p));
    return a;
}
__device__ __forceinline__ float gelu_erf(float v) {
    return 0.5f * v * (1.0f + erff(v * 0.70710678118654752f));
}
__device__ __forceinline__ void mma_bf16(float* c, const uint32_t* a, const uint32_t* b) {
    asm volatile(
        "mma.sync.aligned.m16n8k16.row.col.f32.bf16.bf16.f32 "
        "{%0,%1,%2,%3}, {%4,%5,%6,%7}, {%8,%9}, {%0,%1,%2,%3};"
        : "+f"(c[0]), "+f"(c[1]), "+f"(c[2]), "+f"(c[3])
        : "r"(a[0]), "r"(a[1]), "r"(a[2]), "r"(a[3]), "r"(b[0]), "r"(b[1]));
}
__device__ __forceinline__ void bsplit2(float vx, float vy, uint32_t& hw, uint32_t& lw) {
    __nv_bfloat16 hx = __float2bfloat16(vx);
    __nv_bfloat16 hy = __float2bfloat16(vy);
    __nv_bfloat16 lx = __float2bfloat16(vx - __bfloat162float(hx));
    __nv_bfloat16 ly = __float2bfloat16(vy - __bfloat162float(hy));
    __nv_bfloat162 hp; hp.x = hx; hp.y = hy;
    __nv_bfloat162 lp; lp.x = lx; lp.y = ly;
    hw = *(uint32_t*)&hp;
    lw = *(uint32_t*)&lp;
}

#define FFMA2(accp, ap, bp) \
    asm volatile("fma.rn.f32x2 %0, %1, %2, %0;" : "+l"(accp) : "l"(ap), "l"(bp))
#define PACK_DUP(dst, s) \
    asm("mov.b64 %0, {%1, %1};" : "=l"(dst) : "f"(s))
#define UNPACK2(lo, hi, src) \
    asm("mov.b64 {%0, %1}, %2;" : "=f"(lo), "=f"(hi) : "l"(src))

#define CP16(dst, src) \
    asm volatile("cp.async.cg.shared.global [%0], [%1], 16;" :: "r"(dst), "l"(src) : "memory")
#define CP_COMMIT() asm volatile("cp.async.commit_group;" ::: "memory")
#define CP_WAIT0()  asm volatile("cp.async.wait_group 0;" ::: "memory")
#define CP_WAIT1()  asm volatile("cp.async.wait_group 1;" ::: "memory")

#define LDSM_X4(r0, r1, r2, r3, addr) \
    asm volatile("ldmatrix.sync.aligned.m8n8.x4.shared.b16 {%0,%1,%2,%3}, [%4];" \
        : "=r"(r0), "=r"(r1), "=r"(r2), "=r"(r3) : "r"(addr))
#define LDSM_X2(r0, r1, addr) \
    asm volatile("ldmatrix.sync.aligned.m8n8.x2.shared.b16 {%0,%1}, [%2];" \
        : "=r"(r0), "=r"(r1) : "r"(addr))

#define AKEY(k) (((((k) & 12) >> 2)) | (((k) & 3) << 2))
#define BPRM(s) ((s) ^ (((s) >> 3) & 1))

// ============================================================================
// ENCODER fp32 GEMM — FFMA2 (round-13 version: bit-exact, fastest measured)
// ============================================================================
__global__ __launch_bounds__(256, 2)
void gemm128(const float* __restrict__ A, const float* __restrict__ W,
             const float* __restrict__ bias, const float* __restrict__ res,
             float* __restrict__ C, int K, int N, int epi,
             const float2* __restrict__ stats,
             const float* __restrict__ lng, const float* __restrict__ lnb)
{
    __shared__ __align__(16) float As[2][2048];
    __shared__ __align__(16) float Ws[2][2048];

    const int tid = threadIdx.x;
    const int tx = tid & 15, ty = tid >> 4;
    const size_t row0 = (size_t)blockIdx.y * 128;
    const int col0 = blockIdx.x * 128;

    const int ar0 = tid >> 2, ar1 = ar0 + 64;
    const int ac  = (tid & 3) * 4;
    const int wr0 = tid >> 5, wr1 = wr0 + 8;
    const int ws  = tid & 31;
    const int wsw = BPRM(ws) * 4;
    const int wc  = ws * 4;

    const uint32_t wbase = smem_u32(Ws);

    float2 st0, st1;
    if (stats) {
        st0 = __ldg(stats + row0 + ar0);
        st1 = __ldg(stats + row0 + ar1);
    }

    unsigned long long acc2[8][4];
#pragma unroll
    for (int i = 0; i < 8; i++)
#pragma unroll
        for (int j = 0; j < 4; j++) acc2[i][j] = 0ULL;

    const int bo0 = BPRM(tx * 2) * 4;
    const int bo1 = BPRM(tx * 2 + 1) * 4;

    const int nch = K >> 4;
    float4 av0, av1;

    CP16(wbase + (uint32_t)(0 * 2048 + wr0 * 128 + wsw) * 4, W + (size_t)wr0 * N + col0 + wc);
    CP16(wbase + (uint32_t)(0 * 2048 + wr1 * 128 + wsw) * 4, W + (size_t)wr1 * N + col0 + wc);
    CP_COMMIT();
    av0 = *(const float4*)(A + (row0 + ar0) * K + ac);
    av1 = *(const float4*)(A + (row0 + ar1) * K + ac);
    if (stats) {
        av0.x = fmaf((av0.x - st0.x) * st0.y, __ldg(lng + ac + 0), __ldg(lnb + ac + 0));
        av0.y = fmaf((av0.y - st0.x) * st0.y, __ldg(lng + ac + 1), __ldg(lnb + ac + 1));
        av0.z = fmaf((av0.z - st0.x) * st0.y, __ldg(lng + ac + 2), __ldg(lnb + ac + 2));
        av0.w = fmaf((av0.w - st0.x) * st0.y, __ldg(lng + ac + 3), __ldg(lnb + ac + 3));
        av1.x = fmaf((av1.x - st1.x) * st1.y, __ldg(lng + ac + 0), __ldg(lnb + ac + 0));
        av1.y = fmaf((av1.y - st1.x) * st1.y, __ldg(lng + ac + 1), __ldg(lnb + ac + 1));
        av1.z = fmaf((av1.z - st1.x) * st1.y, __ldg(lng + ac + 2), __ldg(lnb + ac + 2));
        av1.w = fmaf((av1.w - st1.x) * st1.y, __ldg(lng + ac + 3), __ldg(lnb + ac + 3));
    }
    {
        float v0[4] = {av0.x, av0.y, av0.z, av0.w};
        float v1[4] = {av1.x, av1.y, av1.z, av1.w};
#pragma unroll
        for (int j = 0; j < 4; j++) {
            int kidx = ac + j;
            As[0][kidx * 128 + ((((ar0 >> 2) ^ AKEY(kidx)) << 2) | (ar0 & 3))] = v0[j];
            As[0][kidx * 128 + ((((ar1 >> 2) ^ AKEY(kidx)) << 2) | (ar1 & 3))] = v1[j];
        }
    }
    CP_WAIT0();
    __syncthreads();

    for (int c = 0; c < nch; c++) {
        const int buf = c & 1;
        if (c + 1 < nch) {
            const int kk = (c + 1) << 4;
            CP16(wbase + (uint32_t)((buf ^ 1) * 2048 + wr0 * 128 + wsw) * 4,
                 W + (size_t)(kk + wr0) * N + col0 + wc);
            CP16(wbase + (uint32_t)((buf ^ 1) * 2048 + wr1 * 128 + wsw) * 4,
                 W + (size_t)(kk + wr1) * N + col0 + wc);
            CP_COMMIT();
            av0 = *(const float4*)(A + (row0 + ar0) * K + kk + ac);
            av1 = *(const float4*)(A + (row0 + ar1) * K + kk + ac);
        }
#pragma unroll
        for (int k = 0; k < 16; k++) {
            float a[8];
            *(float4*)&a[0] = *(const float4*)&As[buf][k * 128 + (((ty * 2)     ^ AKEY(k)) << 2)];
            *(float4*)&a[4] = *(const float4*)&As[buf][k * 128 + (((ty * 2 + 1) ^ AKEY(k)) << 2)];
            ulonglong2 vb0 = *(const ulonglong2*)&Ws[buf][k * 128 + bo0];
            ulonglong2 vb1 = *(const ulonglong2*)&Ws[buf][k * 128 + bo1];
            unsigned long long b2[4] = {vb0.x, vb0.y, vb1.x, vb1.y};
            unsigned long long a2[8];
#pragma unroll
            for (int i = 0; i < 8; i++) PACK_DUP(a2[i], a[i]);
#pragma unroll
            for (int i = 0; i < 8; i++)
#pragma unroll
                for (int j = 0; j < 4; j++)
                    FFMA2(acc2[i][j], a2[i], b2[j]);
        }
        if (c + 1 < nch) {
            const int kk = (c + 1) << 4;
            if (stats) {
                av0.x = fmaf((av0.x - st0.x) * st0.y, __ldg(lng + kk + ac + 0), __ldg(lnb + kk + ac + 0));
                av0.y = fmaf((av0.y - st0.x) * st0.y, __ldg(lng + kk + ac + 1), __ldg(lnb + kk + ac + 1));
                av0.z = fmaf((av0.z - st0.x) * st0.y, __ldg(lng + kk + ac + 2), __ldg(lnb + kk + ac + 2));
                av0.w = fmaf((av0.w - st0.x) * st0.y, __ldg(lng + kk + ac + 3), __ldg(lnb + kk + ac + 3));
                av1.x = fmaf((av1.x - st1.x) * st1.y, __ldg(lng + kk + ac + 0), __ldg(lnb + kk + ac + 0));
                av1.y = fmaf((av1.y - st1.x) * st1.y, __ldg(lng + kk + ac + 1), __ldg(lnb + kk + ac + 1));
                av1.z = fmaf((av1.z - st1.x) * st1.y, __ldg(lng + kk + ac + 2), __ldg(lnb + kk + ac + 2));
                av1.w = fmaf((av1.w - st1.x) * st1.y, __ldg(lng + kk + ac + 3), __ldg(lnb + kk + ac + 3));
            }
            float v0[4] = {av0.x, av0.y, av0.z, av0.w};
            float v1[4] = {av1.x, av1.y, av1.z, av1.w};
#pragma unroll
            for (int j = 0; j < 4; j++) {
                int kidx = ac + j;
                As[buf ^ 1][kidx * 128 + ((((ar0 >> 2) ^ AKEY(kidx)) << 2) | (ar0 & 3))] = v0[j];
                As[buf ^ 1][kidx * 128 + ((((ar1 >> 2) ^ AKEY(kidx)) << 2) | (ar1 & 3))] = v1[j];
            }
            CP_WAIT0();
        }
        __syncthreads();
    }

    // ---- epilogue: identical values, vectorized float2 I/O ----
#pragma unroll
    for (int i = 0; i < 8; i++) {
        size_t r = row0 + ty * 8 + i;
#pragma unroll
        for (int jc = 0; jc < 4; jc++) {
            float e0, e1;
            UNPACK2(e0, e1, acc2[i][jc]);
            int cix = col0 + tx * 8 + jc * 2;
            float2 bv = __ldg((const float2*)(bias + cix));
            float v0 = e0 + bv.x;
            float v1 = e1 + bv.y;
            if (epi == 1) {
                v0 = 0.5f * v0 * (1.0f + erff(v0 * 0.70710678118654752f));
                v1 = 0.5f * v1 * (1.0f + erff(v1 * 0.70710678118654752f));
            } else if (epi == 2) {
                float2 rv = *(const float2*)(res + r * N + cix);
                v0 += rv.x;
                v1 += rv.y;
            }
            *(float2*)(C + r * N + cix) = make_float2(v0, v1);
        }
    }
}

// ---------------- per-row layernorm stats (encoder) ----------------
__global__ void ln_stats(const float* __restrict__ H, float2* __restrict__ st)
{
    int gw = (int)((blockIdx.x * blockDim.x + threadIdx.x) >> 5);
    int lane = threadIdx.x & 31;
    const float* h = H + (size_t)gw * HID + lane * 8;
    float4 v0 = *(const float4*)h;
    float4 v1 = *(const float4*)(h + 4);
    float v[8] = {v0.x, v0.y, v0.z, v0.w, v1.x, v1.y, v1.z, v1.w};
    float s = 0.f;
#pragma unroll
    for (int k = 0; k < 8; k++) s += v[k];
#pragma unroll
    for (int o = 16; o; o >>= 1) s += __shfl_xor_sync(0xffffffffu, s, o);
    float mu = s * (1.0f / HID);
    float q = 0.f;
#pragma unroll
    for (int k = 0; k < 8; k++) { float d = v[k] - mu; q = fmaf(d, d, q); }
#pragma unroll
    for (int o = 16; o; o >>= 1) q += __shfl_xor_sync(0xffffffffu, q, o);
    float w = rsqrtf(q * (1.0f / HID) + EPSL);
    if (lane == 0) st[gw] = make_float2(mu, w);
}

// ---------------- full layernorm (final norms) ----------------
__global__ void ln_kernel(const float* __restrict__ H, const float* __restrict__ g,
                          const float* __restrict__ b, float* __restrict__ O)
{
    int gw = (int)((blockIdx.x * blockDim.x + threadIdx.x) >> 5);
    int lane = threadIdx.x & 31;
    const float* h = H + (size_t)gw * HID + lane * 8;
    float4 v0 = *(const float4*)h;
    float4 v1 = *(const float4*)(h + 4);
    float v[8] = {v0.x, v0.y, v0.z, v0.w, v1.x, v1.y, v1.z, v1.w};
    float s = 0.f;
#pragma unroll
    for (int k = 0; k < 8; k++) s += v[k];
#pragma unroll
    for (int o = 16; o; o >>= 1) s += __shfl_xor_sync(0xffffffffu, s, o);
    float mu = s * (1.0f / HID);
    float d[8], q = 0.f;
#pragma unroll
    for (int k = 0; k < 8; k++) { d[k] = v[k] - mu; q = fmaf(d[k], d[k], q); }
#pragma unroll
    for (int o = 16; o; o >>= 1) q += __shfl_xor_sync(0xffffffffu, q, o);
    float w = rsqrtf(q * (1.0f / HID) + EPSL);
    const float* gg = g + lane * 8;
    const float* bb = b + lane * 8;
    float o8[8];
#pragma unroll
    for (int k = 0; k < 8; k++) o8[k] = fmaf(d[k] * w, __ldg(gg + k), __ldg(bb + k));
    float* op = O + (size_t)gw * HID + lane * 8;
    *(float4*)op = make_float4(o8[0], o8[1], o8[2], o8[3]);
    *(float4*)(op + 4) = make_float4(o8[4], o8[5], o8[6], o8[7]);
}

// ---------------- layernorm + bf16 hi/lo split (decoder) ----------------
__global__ void ln_split(const float* __restrict__ H, const float* __restrict__ g,
                         const float* __restrict__ b,
                         __nv_bfloat16* __restrict__ Oh, __nv_bfloat16* __restrict__ Ol)
{
    int gw = (int)((blockIdx.x * blockDim.x + threadIdx.x) >> 5);
    int lane = threadIdx.x & 31;
    const float* h = H + (size_t)gw * HID + lane * 8;
    float4 v0 = *(const float4*)h;
    float4 v1 = *(const float4*)(h + 4);
    float v[8] = {v0.x, v0.y, v0.z, v0.w, v1.x, v1.y, v1.z, v1.w};
    float s = 0.f;
#pragma unroll
    for (int k = 0; k < 8; k++) s += v[k];
#pragma unroll
    for (int o = 16; o; o >>= 1) s += __shfl_xor_sync(0xffffffffu, s, o);
    float mu = s * (1.0f / HID);
    float d[8], q = 0.f;
#pragma unroll
    for (int k = 0; k < 8; k++) { d[k] = v[k] - mu; q = fmaf(d[k], d[k], q); }
#pragma unroll
    for (int o = 16; o; o >>= 1) q += __shfl_xor_sync(0xffffffffu, q, o);
    float w = rsqrtf(q * (1.0f / HID) + EPSL);
    const float* gg = g + lane * 8;
    const float* bb = b + lane * 8;
    uint32_t wh[4], wl[4];
#pragma unroll
    for (int p = 0; p < 4; p++) {
        float oa = fmaf(d[2 * p] * w, __ldg(gg + 2 * p), __ldg(bb + 2 * p));
        float ob = fmaf(d[2 * p + 1] * w, __ldg(gg + 2 * p + 1), __ldg(bb + 2 * p + 1));
        bsplit2(oa, ob, wh[p], wl[p]);
    }
    *(uint4*)(Oh + (size_t)gw * HID + lane * 8) = make_uint4(wh[0], wh[1], wh[2], wh[3]);
    *(uint4*)(Ol + (size_t)gw * HID + lane * 8) = make_uint4(wl[0], wl[1], wl[2], wl[3]);
}

// ---------------- small GEMMs (round-13, conflict-free, bit-exact) ---------
template <int K>
__global__ __launch_bounds__(256)
void small_gemm_n256(const float* __restrict__ A, const float* __restrict__ W,
                     const float* __restrict__ bias, float* __restrict__ C)
{
    extern __shared__ float smx[];
    float* sW = smx;
    float* sAT = smx + K * 256;
    const int tid = threadIdx.x;
    const size_t row0 = (size_t)blockIdx.x * 32;
    for (int i = tid; i < K * 256; i += 256) {
        int k = i >> 8, c = i & 255;
        sW[k * 256 + (c ^ ((c >> 5) << 2))] = W[i];
    }
    for (int i = tid; i < 32 * K; i += 256) {
        int r = i / K, k = i - r * K;
        sAT[k * 32 + r] = A[(row0 + r) * K + k];
    }
    __syncthreads();
    const int r = tid >> 3;
    const int qq = tid & 7;
    const int c0 = qq * 32;
    float acc[32];
#pragma unroll
    for (int t = 0; t < 32; t++) acc[t] = 0.f;
#pragma unroll
    for (int k = 0; k < K; k++) {
        float a = sAT[k * 32 + r];
        const float* wrow = sW + k * 256;
#pragma unroll
        for (int j = 0; j < 8; j++) {
            float4 w4 = *(const float4*)(wrow + ((c0 + 4 * j) ^ (qq << 2)));
            acc[4 * j + 0] = fmaf(a, w4.x, acc[4 * j + 0]);
            acc[4 * j + 1] = fmaf(a, w4.y, acc[4 * j + 1]);
            acc[4 * j + 2] = fmaf(a, w4.z, acc[4 * j + 2]);
            acc[4 * j + 3] = fmaf(a, w4.w, acc[4 * j + 3]);
        }
    }
    float* cp = C + (row0 + r) * 256 + c0;
#pragma unroll
    for (int t = 0; t < 32; t++) cp[t] = acc[t] + __ldg(bias + c0 + t);
}

__global__ __launch_bounds__(256)
void small_gemm_n32(const float* __restrict__ A, const float* __restrict__ W,
                    const float* __restrict__ bias, float* __restrict__ C)
{
    extern __shared__ float smx[];
    float* sW = smx;
    float* sAT = smx + 256 * 32;
    const int tid = threadIdx.x;
    const size_t row0 = (size_t)blockIdx.x * 32;
    for (int i = tid; i < 256 * 32; i += 256) sW[i] = W[i];
    for (int i = tid; i < 32 * 256; i += 256) {
        int r = i >> 8, k = i & 255;
        sAT[k * 32 + r] = A[(row0 + r) * 256 + k];
    }
    __syncthreads();
    const int r = tid >> 3;
    const int c0 = (tid & 7) * 4;
    float acc[4] = {0.f, 0.f, 0.f, 0.f};
#pragma unroll
    for (int k = 0; k < 256; k++) {
        float a = sAT[k * 32 + r];
        const float* wr = sW + k * 32 + c0;
#pragma unroll
        for (int t = 0; t < 4; t++) acc[t] = fmaf(a, wr[t], acc[t]);
    }
    float* cp = C + (row0 + r) * 32 + c0;
#pragma unroll
    for (int t = 0; t < 4; t++) cp[t] = acc[t] + __ldg(bias + c0 + t);
}

__global__ __launch_bounds__(256)
void small_gemm_n54(const float* __restrict__ A, const float* __restrict__ W,
                    const float* __restrict__ bias, float* __restrict__ C)
{
    extern __shared__ float smx[];
    float* sW = smx;
    float* sAT = smx + 256 * 54;
    const int tid = threadIdx.x;
    const size_t row0 = (size_t)blockIdx.x * 32;
    for (int i = tid; i < 256 * 54; i += 256) sW[i] = W[i];
    for (int i = tid; i < 32 * 256; i += 256) {
        int r = i >> 8, k = i & 255;
        sAT[k * 32 + r] = A[(row0 + r) * 256 + k];
    }
    __syncthreads();
    const int r = tid >> 3;
    const int c0 = (tid & 7) * 7;
    float acc[7] = {0.f, 0.f, 0.f, 0.f, 0.f, 0.f, 0.f};
#pragma unroll
    for (int k = 0; k < 256; k++) {
        float a = sAT[k * 32 + r];
        const float* wr = sW + k * 54 + c0;
#pragma unroll
        for (int t = 0; t < 7; t++)
            if (c0 + t < 54) acc[t] = fmaf(a, wr[t], acc[t]);
    }
    float* cp = C + (row0 + r) * 54 + c0;
#pragma unroll
    for (int t = 0; t < 7; t++)
        if (c0 + t < 54) cp[t] = acc[t] + __ldg(bias + c0 + t);
}

// ---------------- VQ: 4 rows per warp (round-13, bit-exact indices) --------
__global__ void vq_kernel(const float* __restrict__ Z, const float* __restrict__ CB,
                          float* __restrict__ idx_out, float* __restrict__ zq1,
                          float* __restrict__ zq2, float* __restrict__ part)
{
    extern __shared__ float smx[];
    float* scbT = smx;
    float* sn2 = smx + NC * LAT;
    __shared__ float swsum[8];
    int tid = threadIdx.x;
    for (int i = tid; i < NC * LAT; i += 256) {
        int c = i & (NC - 1);
        int j = i >> 9;
        scbT[j * NC + c] = CB[(size_t)c * LAT + j];
    }
    __syncthreads();
    for (int c = tid; c < NC; c += 256) {
        float s = 0.f;
#pragma unroll
        for (int j = 0; j < LAT; j++) { float t = scbT[j * NC + c]; s = fmaf(t, t, s); }
        sn2[c] = s;
    }
    __syncthreads();

    int warp = tid >> 5, lane = tid & 31;
    float wsum = 0.f;
#pragma unroll 1
    for (int rr4 = 0; rr4 < 4; rr4++) {
        size_t row = (size_t)blockIdx.x * 32 + warp * 4 + rr4;
        const float* z = Z + row * LAT;
        float zv[LAT];
#pragma unroll
        for (int j = 0; j < LAT; j++) zv[j] = z[j];

        float best = 3.4e38f;
        int bidx = 0;
        for (int c = lane; c < NC; c += 32) {
            float s = 0.f;
#pragma unroll
            for (int j = 0; j < LAT; j++) s = fmaf(zv[j], scbT[j * NC + c], s);
            float d2 = sn2[c] - 2.f * s;
            if (d2 < best) { best = d2; bidx = c; }
        }
#pragma unroll
        for (int o = 16; o; o >>= 1) {
            float ob = __shfl_xor_sync(0xffffffffu, best, o);
            int oi = __shfl_xor_sync(0xffffffffu, bidx, o);
            if (ob < best || (ob == best && oi < bidx)) { best = ob; bidx = oi; }
        }
        float zl = z[lane];
        float zq = scbT[lane * NC + bidx];
        float st = zl + (zq - zl);
        zq1[row * LAT + lane] = st;
        zq2[row * LAT + lane] = st;
        float df = zl - zq;
        float ps = df * df;
#pragma unroll
        for (int o = 16; o; o >>= 1) ps += __shfl_xor_sync(0xffffffffu, ps, o);
        if (lane == 0) {
            wsum += ps;
            idx_out[row] = (float)bidx;
        }
    }
    if (lane == 0) swsum[warp] = wsum;
    __syncthreads();
    if (tid == 0) {
        float t = 0.f;
        for (int wq = 0; wq < 8; wq++) t += swsum[wq];
        part[blockIdx.x] = t;
    }
}

__global__ void loss_reduce(const float* __restrict__ part, float* __restrict__ out)
{
    __shared__ float s[1024];
    int tid = threadIdx.x;
    float a = 0.f;
    for (int i = tid; i < Bsz / 32; i += 1024) a += part[i];
    s[tid] = a;
    __syncthreads();
    for (int o = 512; o; o >>= 1) {
        if (tid < o) s[tid] += s[tid + o];
        __syncthreads();
    }
    if (tid == 0) out[0] = s[0] / (float)((size_t)Bsz * LAT);
}

// ---------------- decoder weight prep ----------------
__global__ void tsplitT(const float* __restrict__ W, __nv_bfloat16* __restrict__ Th,
                        __nv_bfloat16* __restrict__ Tl, int K, int N)
{
    int i = blockIdx.x * 256 + threadIdx.x;
    if (i >= K * N) return;
    int n = i / K, k = i - n * K;
    float v = W[(size_t)k * N + n];
    __nv_bfloat16 hb = __float2bfloat16(v);
    Th[i] = hb;
    Tl[i] = __float2bfloat16(v - __bfloat162float(hb));
}

// ============================================================================
// DECODER GEMM — unchanged (at mma-pipe ceiling)
// ============================================================================
#define RST 20

__global__ __launch_bounds__(256, 2)
void mma2(const __nv_bfloat16* __restrict__ Ahg, const __nv_bfloat16* __restrict__ Alg,
          const __nv_bfloat16* __restrict__ Whg, const __nv_bfloat16* __restrict__ Wlg,
          const float* __restrict__ bias, const float* res, float* Cf,
          __nv_bfloat16* Yh, __nv_bfloat16* Yl, int K, int Ntot, int epi)
{
    extern __shared__ __align__(16) uint32_t dsm[];
    const uint32_t sbase = smem_u32(dsm);
    const int tid = threadIdx.x, lane = tid & 31, warp = tid >> 5;
    const int wm = warp >> 2, wn = warp & 3;
    const int q = lane & 3, rr = lane >> 2;
    const size_t row0 = (size_t)blockIdx.y * 128;
    const int n0 = blockIdx.x * 128;

    float acc[4][4][4];
#pragma unroll
    for (int a = 0; a < 4; a++)
#pragma unroll
        for (int b = 0; b < 4; b++)
#pragma unroll
            for (int c = 0; c < 4; c++) acc[a][b][c] = 0.f;

    uint32_t aoff[4], boff[4];
#pragma unroll
    for (int mt = 0; mt < 4; mt++)
        aoff[mt] = (uint32_t)((wm * 64 + mt * 16 + (lane & 15)) * (RST * 4) + (lane >> 4) * 16);
#pragma unroll
    for (int nt = 0; nt < 4; nt++)
        boff[nt] = (uint32_t)((wn * 32 + nt * 8 + (lane & 7)) * (RST * 4) + ((lane >> 3) & 1) * 16);

    auto fill = [&](int kc, int buf) {
        const uint32_t ah_b = sbase + (uint32_t)buf * 10240;
        const uint32_t al_b = sbase + 20480 + (uint32_t)buf * 10240;
        const uint32_t bh_b = sbase + 40960 + (uint32_t)buf * 10240;
        const uint32_t bl_b = sbase + 61440 + (uint32_t)buf * 10240;
#pragma unroll
        for (int i = 0; i < 4; i++) {
            int fid = tid + i * 256;
            int m = fid >> 3, c4 = fid & 3, lo = (fid >> 2) & 1;
            const __nv_bfloat16* s = (lo ? Alg : Ahg) + (row0 + m) * K + kc + c4 * 8;
            CP16((lo ? al_b : ah_b) + (uint32_t)(m * RST + c4 * 4) * 4, s);
        }
#pragma unroll
        for (int i = 0; i < 4; i++) {
            int fid = tid + i * 256;
            int m = fid >> 3, c4 = fid & 3, lo = (fid >> 2) & 1;
            const __nv_bfloat16* s = (lo ? Wlg : Whg) + (size_t)(n0 + m) * K + kc + c4 * 8;
            CP16((lo ? bl_b : bh_b) + (uint32_t)(m * RST + c4 * 4) * 4, s);
        }
    };

    const int nch = K >> 5;
    fill(0, 0);
    CP_COMMIT();
    for (int c = 0; c < nch; c++) {
        if (c + 1 < nch) {
            fill((c + 1) << 5, (c + 1) & 1);
            CP_COMMIT();
            CP_WAIT1();
        } else {
            CP_WAIT0();
        }
        __syncthreads();
        const int buf = c & 1;
        const uint32_t ah_b = sbase + (uint32_t)buf * 10240;
        const uint32_t al_b = sbase + 20480 + (uint32_t)buf * 10240;
        const uint32_t bh_b = sbase + 40960 + (uint32_t)buf * 10240;
        const uint32_t bl_b = sbase + 61440 + (uint32_t)buf * 10240;
#pragma unroll
        for (int ks = 0; ks < 2; ks++) {
            const uint32_t ko = (uint32_t)ks * 32;
            uint32_t ah[4][4], al[4][4], bh[4][2], bl[4][2];
#pragma unroll
            for (int mt = 0; mt < 4; mt++) {
                LDSM_X4(ah[mt][0], ah[mt][1], ah[mt][2], ah[mt][3], ah_b + aoff[mt] + ko);
                LDSM_X4(al[mt][0], al[mt][1], al[mt][2], al[mt][3], al_b + aoff[mt] + ko);
            }
#pragma unroll
            for (int nt = 0; nt < 4; nt++) {
                LDSM_X2(bh[nt][0], bh[nt][1], bh_b + boff[nt] + ko);
                LDSM_X2(bl[nt][0], bl[nt][1], bl_b + boff[nt] + ko);
            }
#pragma unroll
            for (int mt = 0; mt < 4; mt++)
#pragma unroll
                for (int nt = 0; nt < 4; nt++) {
                    mma_bf16(acc[mt][nt], ah[mt], bh[nt]);
                    mma_bf16(acc[mt][nt], ah[mt], bl[nt]);
                    mma_bf16(acc[mt][nt], al[mt], bh[nt]);
                }
        }
        __syncthreads();
    }

#pragma unroll
    for (int mt = 0; mt < 4; mt++) {
        size_t r0 = row0 + wm * 64 + mt * 16 + rr;
        size_t r1 = r0 + 8;
#pragma unroll
        for (int nt = 0; nt < 4; nt++) {
            int gc = n0 + wn * 32 + nt * 8 + q * 2;
            float2 bv = __ldg((const float2*)(bias + gc));
            float v00 = acc[mt][nt][0] + bv.x;
            float v01 = acc[mt][nt][1] + bv.y;
            float v10 = acc[mt][nt][2] + bv.x;
            float v11 = acc[mt][nt][3] + bv.y;
            if (epi == 1) {
                v00 = gelu_erf(v00); v01 = gelu_erf(v01);
                v10 = gelu_erf(v10); v11 = gelu_erf(v11);
                uint32_t h0, l0, h1, l1;
                bsplit2(v00, v01, h0, l0);
                bsplit2(v10, v11, h1, l1);
                *(uint32_t*)(Yh + r0 * Ntot + gc) = h0;
                *(uint32_t*)(Yl + r0 * Ntot + gc) = l0;
                *(uint32_t*)(Yh + r1 * Ntot + gc) = h1;
                *(uint32_t*)(Yl + r1 * Ntot + gc) = l1;
            } else {
                float2 rv0 = *(const float2*)(res + r0 * Ntot + gc);
                float2 rv1 = *(const float2*)(res + r1 * Ntot + gc);
                v00 += rv0.x; v01 += rv0.y; v10 += rv1.x; v11 += rv1.y;
                *(float2*)(Cf + r0 * Ntot + gc) = make_float2(v00, v01);
                *(float2*)(Cf + r1 * Ntot + gc) = make_float2(v10, v11);
            }
        }
    }
}

// ---------------- orchestration ----------------
extern "C" void kernel_launch(void* const* d_in, const int* in_sizes, int n_in,
                              void* d_out, int out_size)
{
    const float* x    = (const float*)d_in[0];
    const float* epw  = (const float*)d_in[1];
    const float* epb  = (const float*)d_in[2];
    const float* elng = (const float*)d_in[3];
    const float* elnb = (const float*)d_in[4];
    const float* ew1  = (const float*)d_in[5];
    const float* eb1  = (const float*)d_in[6];
    const float* ew2  = (const float*)d_in[7];
    const float* eb2  = (const float*)d_in[8];
    const float* eng  = (const float*)d_in[9];
    const float* enb  = (const float*)d_in[10];
    const float* elw  = (const float*)d_in[11];
    const float* elb  = (const float*)d_in[12];
    const float* cb   = (const float*)d_in[13];
    const float* dlw  = (const float*)d_in[14];
    const float* dlb  = (const float*)d_in[15];
    const float* dlng = (const float*)d_in[16];
    const float* dlnb = (const float*)d_in[17];
    const float* dw1  = (const float*)d_in[18];
    const float* db1  = (const float*)d_in[19];
    const float* dw2  = (const float*)d_in[20];
    const float* db2  = (const float*)d_in[21];
    const float* dng  = (const float*)d_in[22];
    const float* dnb  = (const float*)d_in[23];
    const float* dpw  = (const float*)d_in[24];
    const float* dpb  = (const float*)d_in[25];

    float* out = (float*)d_out;
    float* o_xrec = out;
    float* o_zq   = out + (size_t)Bsz * IN_D;
    float* o_idx  = o_zq + (size_t)Bsz * LAT;
    float* o_loss = o_idx + (size_t)Bsz;

    float *h, *hn, *y, *z, *zq, *part, *stats;
    __nv_bfloat16 *wh16, *wl16, *ah16, *al16;
    cudaGetSymbolAddress((void**)&h, g_h);
    cudaGetSymbolAddress((void**)&hn, g_hn);
    cudaGetSymbolAddress((void**)&y, g_y);
    cudaGetSymbolAddress((void**)&z, g_z);
    cudaGetSymbolAddress((void**)&zq, g_zq);
    cudaGetSymbolAddress((void**)&part, g_part);
    cudaGetSymbolAddress((void**)&stats, g_stats);
    cudaGetSymbolAddress((void**)&wh16, g_wh16);
    cudaGetSymbolAddress((void**)&wl16, g_wl16);
    cudaGetSymbolAddress((void**)&ah16, g_ah16);
    cudaGetSymbolAddress((void**)&al16, g_al16);

    __nv_bfloat16* yh16 = (__nv_bfloat16*)y;
    __nv_bfloat16* yl16 = yh16 + (size_t)Bsz * EXPD;

    const int MMA_SMEM = 81920;
    cudaFuncSetAttribute(mma2, cudaFuncAttributeMaxDynamicSharedMemorySize, MMA_SMEM);
    cudaFuncSetAttribute(vq_kernel, cudaFuncAttributeMaxDynamicSharedMemorySize, 70656);
    const int SM_N256_54 = (54 * 256 + 32 * 54) * 4;
    const int SM_N256_32 = (32 * 256 + 32 * 32) * 4;
    const int SM_N32     = (256 * 32 + 256 * 32) * 4;
    const int SM_N54     = (256 * 54 + 256 * 32) * 4;
    cudaFuncSetAttribute(small_gemm_n256<54>, cudaFuncAttributeMaxDynamicSharedMemorySize, SM_N256_54);
    cudaFuncSetAttribute(small_gemm_n256<32>, cudaFuncAttributeMaxDynamicSharedMemorySize, SM_N256_32);
    cudaFuncSetAttribute(small_gemm_n32, cudaFuncAttributeMaxDynamicSharedMemorySize, SM_N32);
    cudaFuncSetAttribute(small_gemm_n54, cudaFuncAttributeMaxDynamicSharedMemorySize, SM_N54);

    const size_t WSZ = 131072;
    const size_t OW1D = 0, OW2D = 4 * WSZ;

    // ---- encoder: frozen FFMA2 fp32 path (bit-identical z -> indices) ----
    small_gemm_n256<54><<<Bsz / 32, 256, SM_N256_54>>>(x, epw, epb, h);
    for (int i = 0; i < NB; i++) {
        ln_stats<<<Bsz / 8, 256>>>(h, (float2*)stats);
        gemm128<<<dim3(EXPD / 128, Bsz / 128), 256>>>(
            h, ew1 + (size_t)i * HID * EXPD, eb1 + i * EXPD, nullptr, y, HID, EXPD, 1,
            (const float2*)stats, elng + i * HID, elnb + i * HID);
        gemm128<<<dim3(HID / 128, Bsz / 128), 256>>>(
            y, ew2 + (size_t)i * EXPD * HID, eb2 + i * HID, h, h, EXPD, HID, 2,
            nullptr, nullptr, nullptr);
    }
    ln_kernel<<<Bsz / 8, 256>>>(h, eng, enb, hn);
    small_gemm_n32<<<Bsz / 32, 256, SM_N32>>>(hn, elw, elb, z);

    // ---- VQ ----
    vq_kernel<<<Bsz / 32, 256, (NC * LAT + NC) * 4>>>(z, cb, o_idx, o_zq, zq, part);
    loss_reduce<<<1, 1024>>>(part, o_loss);

    // ---- decoder weight prep ----
    for (int i = 0; i < NB; i++) {
        tsplitT<<<512, 256>>>(dw1 + i * WSZ, wh16 + OW1D + i * WSZ, wl16 + OW1D + i * WSZ, HID, EXPD);
        tsplitT<<<512, 256>>>(dw2 + i * WSZ, wh16 + OW2D + i * WSZ, wl16 + OW2D + i * WSZ, EXPD, HID);
    }

    // ---- decoder: bf16 split mma pipeline (unchanged) ----
    small_gemm_n256<32><<<Bsz / 32, 256, SM_N256_32>>>(zq, dlw, dlb, h);
    for (int i = 0; i < NB; i++) {
        ln_split<<<Bsz / 8, 256>>>(h, dlng + i * HID, dlnb + i * HID, ah16, al16);
        mma2<<<dim3(EXPD / 128, Bsz / 128), 256, MMA_SMEM>>>(
            ah16, al16, wh16 + OW1D + i * WSZ, wl16 + OW1D + i * WSZ, db1 + i * EXPD,
            nullptr, nullptr, yh16, yl16, HID, EXPD, 1);
        mma2<<<dim3(HID / 128, Bsz / 128), 256, MMA_SMEM>>>(
            yh16, yl16, wh16 + OW2D + i * WSZ, wl16 + OW2D + i * WSZ, db2 + i * HID,
            h, h, nullptr, nullptr, EXPD, HID, 2);
    }
    ln_kernel<<<Bsz / 8, 256>>>(h, dng, dnb, hn);
    small_gemm_n54<<<Bsz / 32, 256, SM_N54>>>(hn, dpw, dpb, o_xrec);
}

// round 16
// speedup vs baseline: 1.1351x; 1.0225x over previous
#include <cuda_runtime.h>
#include <cuda_bf16.h>
#include <math.h>
#include <stdint.h>

#define Bsz 262144
#define IN_D 54
#define HID 256
#define EXPD 512
#define LAT 32
#define NB 4
#define NC 512
#define EPSL 1e-5f

// ---------------- scratch (device globals: allocation-free) ----------------
__device__ float g_h [(size_t)Bsz * HID];
__device__ float g_y [(size_t)Bsz * EXPD];
__device__ float g_z [(size_t)Bsz * LAT];
__device__ float g_zq[(size_t)Bsz * LAT];
__device__ float g_part[Bsz / 32];
__device__ float g_stats[(size_t)Bsz * 2];
__device__ __nv_bfloat16 g_wh16[1048576];
__device__ __nv_bfloat16 g_wl16[1048576];
__device__ __nv_bfloat16 g_ah16[(size_t)Bsz * HID];
__device__ __nv_bfloat16 g_al16[(size_t)Bsz * HID];

// ---------------- helpers ----------------
__device__ __forceinline__ uint32_t smem_u32(const void* p) {
    uint32_t a;
    asm("{ .reg .u64 t; cvta.to.shared.u64 t, %1; cvt.u32.u64 %0, t; }" : "=r"(a) : "l"(p));
    return a;
}
__device__ __forceinline__ float gelu_erf(float v) {
    return 0.5f * v * (1.0f + erff(v * 0.70710678118654752f));
}
__device__ __forceinline__ void mma_bf16(float* c, const uint32_t* a, const uint32_t* b) {
    asm volatile(
        "mma.sync.aligned.m16n8k16.row.col.f32.bf16.bf16.f32 "
        "{%0,%1,%2,%3}, {%4,%5,%6,%7}, {%8,%9}, {%0,%1,%2,%3};"
        : "+f"(c[0]), "+f"(c[1]), "+f"(c[2]), "+f"(c[3])
        : "r"(a[0]), "r"(a[1]), "r"(a[2]), "r"(a[3]), "r"(b[0]), "r"(b[1]));
}
__device__ __forceinline__ void bsplit2(float vx, float vy, uint32_t& hw, uint32_t& lw) {
    __nv_bfloat16 hx = __float2bfloat16(vx);
    __nv_bfloat16 hy = __float2bfloat16(vy);
    __nv_bfloat16 lx = __float2bfloat16(vx - __bfloat162float(hx));
    __nv_bfloat16 ly = __float2bfloat16(vy - __bfloat162float(hy));
    __nv_bfloat162 hp; hp.x = hx; hp.y = hy;
    __nv_bfloat162 lp; lp.x = lx; lp.y = ly;
    hw = *(uint32_t*)&hp;
    lw = *(uint32_t*)&lp;
}

#define FFMA2(accp, ap, bp) \
    asm volatile("fma.rn.f32x2 %0, %1, %2, %0;" : "+l"(accp) : "l"(ap), "l"(bp))
#define PACK_DUP(dst, s) \
    asm("mov.b64 %0, {%1, %1};" : "=l"(dst) : "f"(s))
#define UNPACK2(lo, hi, src) \
    asm("mov.b64 {%0, %1}, %2;" : "=f"(lo), "=f"(hi) : "l"(src))

#define CP16(dst, src) \
    asm volatile("cp.async.cg.shared.global [%0], [%1], 16;" :: "r"(dst), "l"(src) : "memory")
#define CP_COMMIT() asm volatile("cp.async.commit_group;" ::: "memory")
#define CP_WAIT0()  asm volatile("cp.async.wait_group 0;" ::: "memory")
#define CP_WAIT1()  asm volatile("cp.async.wait_group 1;" ::: "memory")

#define LDSM_X4(r0, r1, r2, r3, addr) \
    asm volatile("ldmatrix.sync.aligned.m8n8.x4.shared.b16 {%0,%1,%2,%3}, [%4];" \
        : "=r"(r0), "=r"(r1), "=r"(r2), "=r"(r3) : "r"(addr))
#define LDSM_X2(r0, r1, addr) \
    asm volatile("ldmatrix.sync.aligned.m8n8.x2.shared.b16 {%0,%1}, [%2];" \
        : "=r"(r0), "=r"(r1) : "r"(addr))

#define AKEY(k) (((((k) & 12) >> 2)) | (((k) & 3) << 2))
#define BPRM(s) ((s) ^ (((s) >> 3) & 1))

// ============================================================================
// ENCODER fp32 GEMM — FFMA2 (round-13/15 version, byte-identical: bit-exact)
// ============================================================================
__global__ __launch_bounds__(256, 2)
void gemm128(const float* __restrict__ A, const float* __restrict__ W,
             const float* __restrict__ bias, const float* __restrict__ res,
             float* __restrict__ C, int K, int N, int epi,
             const float2* __restrict__ stats,
             const float* __restrict__ lng, const float* __restrict__ lnb)
{
    __shared__ __align__(16) float As[2][2048];
    __shared__ __align__(16) float Ws[2][2048];

    const int tid = threadIdx.x;
    const int tx = tid & 15, ty = tid >> 4;
    const size_t row0 = (size_t)blockIdx.y * 128;
    const int col0 = blockIdx.x * 128;

    const int ar0 = tid >> 2, ar1 = ar0 + 64;
    const int ac  = (tid & 3) * 4;
    const int wr0 = tid >> 5, wr1 = wr0 + 8;
    const int ws  = tid & 31;
    const int wsw = BPRM(ws) * 4;
    const int wc  = ws * 4;

    const uint32_t wbase = smem_u32(Ws);

    float2 st0, st1;
    if (stats) {
        st0 = __ldg(stats + row0 + ar0);
        st1 = __ldg(stats + row0 + ar1);
    }

    unsigned long long acc2[8][4];
#pragma unroll
    for (int i = 0; i < 8; i++)
#pragma unroll
        for (int j = 0; j < 4; j++) acc2[i][j] = 0ULL;

    const int bo0 = BPRM(tx * 2) * 4;
    const int bo1 = BPRM(tx * 2 + 1) * 4;

    const int nch = K >> 4;
    float4 av0, av1;

    CP16(wbase + (uint32_t)(0 * 2048 + wr0 * 128 + wsw) * 4, W + (size_t)wr0 * N + col0 + wc);
    CP16(wbase + (uint32_t)(0 * 2048 + wr1 * 128 + wsw) * 4, W + (size_t)wr1 * N + col0 + wc);
    CP_COMMIT();
    av0 = *(const float4*)(A + (row0 + ar0) * K + ac);
    av1 = *(const float4*)(A + (row0 + ar1) * K + ac);
    if (stats) {
        av0.x = fmaf((av0.x - st0.x) * st0.y, __ldg(lng + ac + 0), __ldg(lnb + ac + 0));
        av0.y = fmaf((av0.y - st0.x) * st0.y, __ldg(lng + ac + 1), __ldg(lnb + ac + 1));
        av0.z = fmaf((av0.z - st0.x) * st0.y, __ldg(lng + ac + 2), __ldg(lnb + ac + 2));
        av0.w = fmaf((av0.w - st0.x) * st0.y, __ldg(lng + ac + 3), __ldg(lnb + ac + 3));
        av1.x = fmaf((av1.x - st1.x) * st1.y, __ldg(lng + ac + 0), __ldg(lnb + ac + 0));
        av1.y = fmaf((av1.y - st1.x) * st1.y, __ldg(lng + ac + 1), __ldg(lnb + ac + 1));
        av1.z = fmaf((av1.z - st1.x) * st1.y, __ldg(lng + ac + 2), __ldg(lnb + ac + 2));
        av1.w = fmaf((av1.w - st1.x) * st1.y, __ldg(lng + ac + 3), __ldg(lnb + ac + 3));
    }
    {
        float v0[4] = {av0.x, av0.y, av0.z, av0.w};
        float v1[4] = {av1.x, av1.y, av1.z, av1.w};
#pragma unroll
        for (int j = 0; j < 4; j++) {
            int kidx = ac + j;
            As[0][kidx * 128 + ((((ar0 >> 2) ^ AKEY(kidx)) << 2) | (ar0 & 3))] = v0[j];
            As[0][kidx * 128 + ((((ar1 >> 2) ^ AKEY(kidx)) << 2) | (ar1 & 3))] = v1[j];
        }
    }
    CP_WAIT0();
    __syncthreads();

    for (int c = 0; c < nch; c++) {
        const int buf = c & 1;
        if (c + 1 < nch) {
            const int kk = (c + 1) << 4;
            CP16(wbase + (uint32_t)((buf ^ 1) * 2048 + wr0 * 128 + wsw) * 4,
                 W + (size_t)(kk + wr0) * N + col0 + wc);
            CP16(wbase + (uint32_t)((buf ^ 1) * 2048 + wr1 * 128 + wsw) * 4,
                 W + (size_t)(kk + wr1) * N + col0 + wc);
            CP_COMMIT();
            av0 = *(const float4*)(A + (row0 + ar0) * K + kk + ac);
            av1 = *(const float4*)(A + (row0 + ar1) * K + kk + ac);
        }
#pragma unroll
        for (int k = 0; k < 16; k++) {
            float a[8];
            *(float4*)&a[0] = *(const float4*)&As[buf][k * 128 + (((ty * 2)     ^ AKEY(k)) << 2)];
            *(float4*)&a[4] = *(const float4*)&As[buf][k * 128 + (((ty * 2 + 1) ^ AKEY(k)) << 2)];
            ulonglong2 vb0 = *(const ulonglong2*)&Ws[buf][k * 128 + bo0];
            ulonglong2 vb1 = *(const ulonglong2*)&Ws[buf][k * 128 + bo1];
            unsigned long long b2[4] = {vb0.x, vb0.y, vb1.x, vb1.y};
            unsigned long long a2[8];
#pragma unroll
            for (int i = 0; i < 8; i++) PACK_DUP(a2[i], a[i]);
#pragma unroll
            for (int i = 0; i < 8; i++)
#pragma unroll
                for (int j = 0; j < 4; j++)
                    FFMA2(acc2[i][j], a2[i], b2[j]);
        }
        if (c + 1 < nch) {
            const int kk = (c + 1) << 4;
            if (stats) {
                av0.x = fmaf((av0.x - st0.x) * st0.y, __ldg(lng + kk + ac + 0), __ldg(lnb + kk + ac + 0));
                av0.y = fmaf((av0.y - st0.x) * st0.y, __ldg(lng + kk + ac + 1), __ldg(lnb + kk + ac + 1));
                av0.z = fmaf((av0.z - st0.x) * st0.y, __ldg(lng + kk + ac + 2), __ldg(lnb + kk + ac + 2));
                av0.w = fmaf((av0.w - st0.x) * st0.y, __ldg(lng + kk + ac + 3), __ldg(lnb + kk + ac + 3));
                av1.x = fmaf((av1.x - st1.x) * st1.y, __ldg(lng + kk + ac + 0), __ldg(lnb + kk + ac + 0));
                av1.y = fmaf((av1.y - st1.x) * st1.y, __ldg(lng + kk + ac + 1), __ldg(lnb + kk + ac + 1));
                av1.z = fmaf((av1.z - st1.x) * st1.y, __ldg(lng + kk + ac + 2), __ldg(lnb + kk + ac + 2));
                av1.w = fmaf((av1.w - st1.x) * st1.y, __ldg(lng + kk + ac + 3), __ldg(lnb + kk + ac + 3));
            }
            float v0[4] = {av0.x, av0.y, av0.z, av0.w};
            float v1[4] = {av1.x, av1.y, av1.z, av1.w};
#pragma unroll
            for (int j = 0; j < 4; j++) {
                int kidx = ac + j;
                As[buf ^ 1][kidx * 128 + ((((ar0 >> 2) ^ AKEY(kidx)) << 2) | (ar0 & 3))] = v0[j];
                As[buf ^ 1][kidx * 128 + ((((ar1 >> 2) ^ AKEY(kidx)) << 2) | (ar1 & 3))] = v1[j];
            }
            CP_WAIT0();
        }
        __syncthreads();
    }

#pragma unroll
    for (int i = 0; i < 8; i++) {
        size_t r = row0 + ty * 8 + i;
#pragma unroll
        for (int jc = 0; jc < 4; jc++) {
            float e0, e1;
            UNPACK2(e0, e1, acc2[i][jc]);
            int cix = col0 + tx * 8 + jc * 2;
            float2 bv = __ldg((const float2*)(bias + cix));
            float v0 = e0 + bv.x;
            float v1 = e1 + bv.y;
            if (epi == 1) {
                v0 = 0.5f * v0 * (1.0f + erff(v0 * 0.70710678118654752f));
                v1 = 0.5f * v1 * (1.0f + erff(v1 * 0.70710678118654752f));
            } else if (epi == 2) {
                float2 rv = *(const float2*)(res + r * N + cix);
                v0 += rv.x;
                v1 += rv.y;
            }
            *(float2*)(C + r * N + cix) = make_float2(v0, v1);
        }
    }
}

// ---------------- per-row layernorm stats (encoder) ----------------
__global__ void ln_stats(const float* __restrict__ H, float2* __restrict__ st)
{
    int gw = (int)((blockIdx.x * blockDim.x + threadIdx.x) >> 5);
    int lane = threadIdx.x & 31;
    const float* h = H + (size_t)gw * HID + lane * 8;
    float4 v0 = *(const float4*)h;
    float4 v1 = *(const float4*)(h + 4);
    float v[8] = {v0.x, v0.y, v0.z, v0.w, v1.x, v1.y, v1.z, v1.w};
    float s = 0.f;
#pragma unroll
    for (int k = 0; k < 8; k++) s += v[k];
#pragma unroll
    for (int o = 16; o; o >>= 1) s += __shfl_xor_sync(0xffffffffu, s, o);
    float mu = s * (1.0f / HID);
    float q = 0.f;
#pragma unroll
    for (int k = 0; k < 8; k++) { float d = v[k] - mu; q = fmaf(d, d, q); }
#pragma unroll
    for (int o = 16; o; o >>= 1) q += __shfl_xor_sync(0xffffffffu, q, o);
    float w = rsqrtf(q * (1.0f / HID) + EPSL);
    if (lane == 0) st[gw] = make_float2(mu, w);
}

// ---------------- layernorm + bf16 hi/lo split (decoder) ----------------
__global__ void ln_split(const float* __restrict__ H, const float* __restrict__ g,
                         const float* __restrict__ b,
                         __nv_bfloat16* __restrict__ Oh, __nv_bfloat16* __restrict__ Ol)
{
    int gw = (int)((blockIdx.x * blockDim.x + threadIdx.x) >> 5);
    int lane = threadIdx.x & 31;
    const float* h = H + (size_t)gw * HID + lane * 8;
    float4 v0 = *(const float4*)h;
    float4 v1 = *(const float4*)(h + 4);
    float v[8] = {v0.x, v0.y, v0.z, v0.w, v1.x, v1.y, v1.z, v1.w};
    float s = 0.f;
#pragma unroll
    for (int k = 0; k < 8; k++) s += v[k];
#pragma unroll
    for (int o = 16; o; o >>= 1) s += __shfl_xor_sync(0xffffffffu, s, o);
    float mu = s * (1.0f / HID);
    float d[8], q = 0.f;
#pragma unroll
    for (int k = 0; k < 8; k++) { d[k] = v[k] - mu; q = fmaf(d[k], d[k], q); }
#pragma unroll
    for (int o = 16; o; o >>= 1) q += __shfl_xor_sync(0xffffffffu, q, o);
    float w = rsqrtf(q * (1.0f / HID) + EPSL);
    const float* gg = g + lane * 8;
    const float* bb = b + lane * 8;
    uint32_t wh[4], wl[4];
#pragma unroll
    for (int p = 0; p < 4; p++) {
        float oa = fmaf(d[2 * p] * w, __ldg(gg + 2 * p), __ldg(bb + 2 * p));
        float ob = fmaf(d[2 * p + 1] * w, __ldg(gg + 2 * p + 1), __ldg(bb + 2 * p + 1));
        bsplit2(oa, ob, wh[p], wl[p]);
    }
    *(uint4*)(Oh + (size_t)gw * HID + lane * 8) = make_uint4(wh[0], wh[1], wh[2], wh[3]);
    *(uint4*)(Ol + (size_t)gw * HID + lane * 8) = make_uint4(wl[0], wl[1], wl[2], wl[3]);
}

// ---------------- small GEMM N=256 (enc_proj / dec in-proj) ----------------
template <int K>
__global__ __launch_bounds__(256)
void small_gemm_n256(const float* __restrict__ A, const float* __restrict__ W,
                     const float* __restrict__ bias, float* __restrict__ C)
{
    extern __shared__ float smx[];
    float* sW = smx;
    float* sAT = smx + K * 256;
    const int tid = threadIdx.x;
    const size_t row0 = (size_t)blockIdx.x * 32;
    for (int i = tid; i < K * 256; i += 256) {
        int k = i >> 8, c = i & 255;
        sW[k * 256 + (c ^ ((c >> 5) << 2))] = W[i];
    }
    for (int i = tid; i < 32 * K; i += 256) {
        int r = i / K, k = i - r * K;
        sAT[k * 32 + r] = A[(row0 + r) * K + k];
    }
    __syncthreads();
    const int r = tid >> 3;
    const int qq = tid & 7;
    const int c0 = qq * 32;
    float acc[32];
#pragma unroll
    for (int t = 0; t < 32; t++) acc[t] = 0.f;
#pragma unroll
    for (int k = 0; k < K; k++) {
        float a = sAT[k * 32 + r];
        const float* wrow = sW + k * 256;
#pragma unroll
        for (int j = 0; j < 8; j++) {
            float4 w4 = *(const float4*)(wrow + ((c0 + 4 * j) ^ (qq << 2)));
            acc[4 * j + 0] = fmaf(a, w4.x, acc[4 * j + 0]);
            acc[4 * j + 1] = fmaf(a, w4.y, acc[4 * j + 1]);
            acc[4 * j + 2] = fmaf(a, w4.z, acc[4 * j + 2]);
            acc[4 * j + 3] = fmaf(a, w4.w, acc[4 * j + 3]);
        }
    }
    float* cp = C + (row0 + r) * 256 + c0;
#pragma unroll
    for (int t = 0; t < 32; t++) cp[t] = acc[t] + __ldg(bias + c0 + t);
}

// ============================================================================
// FUSED final-LN + projection kernels. Per-row LN ops verbatim (bit-exact hn);
// gemm fmaf chain identical (k ascending). hn lives only in SMEM.
// ============================================================================
#define HST 260   // hn row stride in SMEM (padded)

// N=32, K=256 (encoder: LN(h; g,b) @ elw + elb -> z)
__global__ __launch_bounds__(256)
void ln_gemm_n32(const float* __restrict__ H, const float* __restrict__ g,
                 const float* __restrict__ b, const float* __restrict__ W,
                 const float* __restrict__ bias, float* __restrict__ C)
{
    extern __shared__ float smx[];
    float* sW = smx;               // [256][32]
    float* sA = smx + 256 * 32;    // [32][HST]
    const int tid = threadIdx.x;
    const int warp = tid >> 5, lane = tid & 31;
    const size_t row0 = (size_t)blockIdx.x * 32;
    for (int i = tid; i < 256 * 32; i += 256) sW[i] = W[i];
    // LN: each warp handles 4 rows, per-row math identical to ln_kernel
#pragma unroll 1
    for (int rr = 0; rr < 4; rr++) {
        int r = warp * 4 + rr;
        const float* h = H + (row0 + r) * HID + lane * 8;
        float4 v0 = *(const float4*)h;
        float4 v1 = *(const float4*)(h + 4);
        float v[8] = {v0.x, v0.y, v0.z, v0.w, v1.x, v1.y, v1.z, v1.w};
        float s = 0.f;
#pragma unroll
        for (int k = 0; k < 8; k++) s += v[k];
#pragma unroll
        for (int o = 16; o; o >>= 1) s += __shfl_xor_sync(0xffffffffu, s, o);
        float mu = s * (1.0f / HID);
        float d[8], q = 0.f;
#pragma unroll
        for (int k = 0; k < 8; k++) { d[k] = v[k] - mu; q = fmaf(d[k], d[k], q); }
#pragma unroll
        for (int o = 16; o; o >>= 1) q += __shfl_xor_sync(0xffffffffu, q, o);
        float w = rsqrtf(q * (1.0f / HID) + EPSL);
        const float* gg = g + lane * 8;
        const float* bb = b + lane * 8;
        float o8[8];
#pragma unroll
        for (int k = 0; k < 8; k++) o8[k] = fmaf(d[k] * w, __ldg(gg + k), __ldg(bb + k));
        float* dst = sA + r * HST + lane * 8;
        *(float4*)dst = make_float4(o8[0], o8[1], o8[2], o8[3]);
        *(float4*)(dst + 4) = make_float4(o8[4], o8[5], o8[6], o8[7]);
    }
    __syncthreads();
    const int r = tid >> 3;
    const int c0 = (tid & 7) * 4;
    float acc[4] = {0.f, 0.f, 0.f, 0.f};
#pragma unroll
    for (int k = 0; k < 256; k++) {
        float a = sA[r * HST + k];
        const float* wr = sW + k * 32 + c0;
#pragma unroll
        for (int t = 0; t < 4; t++) acc[t] = fmaf(a, wr[t], acc[t]);
    }
    float* cp = C + (row0 + r) * 32 + c0;
#pragma unroll
    for (int t = 0; t < 4; t++) cp[t] = acc[t] + __ldg(bias + c0 + t);
}

// N=54, K=256 (decoder: LN(h; g,b) @ dpw + dpb -> x_recon)
__global__ __launch_bounds__(256)
void ln_gemm_n54(const float* __restrict__ H, const float* __restrict__ g,
                 const float* __restrict__ b, const float* __restrict__ W,
                 const float* __restrict__ bias, float* __restrict__ C)
{
    extern __shared__ float smx[];
    float* sW = smx;               // [256][54]
    float* sA = smx + 256 * 54;    // [32][HST]
    const int tid = threadIdx.x;
    const int warp = tid >> 5, lane = tid & 31;
    const size_t row0 = (size_t)blockIdx.x * 32;
    for (int i = tid; i < 256 * 54; i += 256) sW[i] = W[i];
#pragma unroll 1
    for (int rr = 0; rr < 4; rr++) {
        int r = warp * 4 + rr;
        const float* h = H + (row0 + r) * HID + lane * 8;
        float4 v0 = *(const float4*)h;
        float4 v1 = *(const float4*)(h + 4);
        float v[8] = {v0.x, v0.y, v0.z, v0.w, v1.x, v1.y, v1.z, v1.w};
        float s = 0.f;
#pragma unroll
        for (int k = 0; k < 8; k++) s += v[k];
#pragma unroll
        for (int o = 16; o; o >>= 1) s += __shfl_xor_sync(0xffffffffu, s, o);
        float mu = s * (1.0f / HID);
        float d[8], q = 0.f;
#pragma unroll
        for (int k = 0; k < 8; k++) { d[k] = v[k] - mu; q = fmaf(d[k], d[k], q); }
#pragma unroll
        for (int o = 16; o; o >>= 1) q += __shfl_xor_sync(0xffffffffu, q, o);
        float w = rsqrtf(q * (1.0f / HID) + EPSL);
        const float* gg = g + lane * 8;
        const float* bb = b + lane * 8;
        float o8[8];
#pragma unroll
        for (int k = 0; k < 8; k++) o8[k] = fmaf(d[k] * w, __ldg(gg + k), __ldg(bb + k));
        float* dst = sA + r * HST + lane * 8;
        *(float4*)dst = make_float4(o8[0], o8[1], o8[2], o8[3]);
        *(float4*)(dst + 4) = make_float4(o8[4], o8[5], o8[6], o8[7]);
    }
    __syncthreads();
    const int r = tid >> 3;
    const int c0 = (tid & 7) * 7;
    float acc[7] = {0.f, 0.f, 0.f, 0.f, 0.f, 0.f, 0.f};
#pragma unroll
    for (int k = 0; k < 256; k++) {
        float a = sA[r * HST + k];
        const float* wr = sW + k * 54 + c0;
#pragma unroll
        for (int t = 0; t < 7; t++)
            if (c0 + t < 54) acc[t] = fmaf(a, wr[t], acc[t]);
    }
    float* cp = C + (row0 + r) * 54 + c0;
#pragma unroll
    for (int t = 0; t < 7; t++)
        if (c0 + t < 54) cp[t] = acc[t] + __ldg(bias + c0 + t);
}

// ---------------- VQ: 4 rows per warp (bit-exact indices) ------------------
__global__ void vq_kernel(const float* __restrict__ Z, const float* __restrict__ CB,
                          float* __restrict__ idx_out, float* __restrict__ zq1,
                          float* __restrict__ zq2, float* __restrict__ part)
{
    extern __shared__ float smx[];
    float* scbT = smx;
    float* sn2 = smx + NC * LAT;
    __shared__ float swsum[8];
    int tid = threadIdx.x;
    for (int i = tid; i < NC * LAT; i += 256) {
        int c = i & (NC - 1);
        int j = i >> 9;
        scbT[j * NC + c] = CB[(size_t)c * LAT + j];
    }
    __syncthreads();
    for (int c = tid; c < NC; c += 256) {
        float s = 0.f;
#pragma unroll
        for (int j = 0; j < LAT; j++) { float t = scbT[j * NC + c]; s = fmaf(t, t, s); }
        sn2[c] = s;
    }
    __syncthreads();

    int warp = tid >> 5, lane = tid & 31;
    float wsum = 0.f;
#pragma unroll 1
    for (int rr4 = 0; rr4 < 4; rr4++) {
        size_t row = (size_t)blockIdx.x * 32 + warp * 4 + rr4;
        const float* z = Z + row * LAT;
        float zv[LAT];
#pragma unroll
        for (int j = 0; j < LAT; j++) zv[j] = z[j];

        float best = 3.4e38f;
        int bidx = 0;
        for (int c = lane; c < NC; c += 32) {
            float s = 0.f;
#pragma unroll
            for (int j = 0; j < LAT; j++) s = fmaf(zv[j], scbT[j * NC + c], s);
            float d2 = sn2[c] - 2.f * s;
            if (d2 < best) { best = d2; bidx = c; }
        }
#pragma unroll
        for (int o = 16; o; o >>= 1) {
            float ob = __shfl_xor_sync(0xffffffffu, best, o);
            int oi = __shfl_xor_sync(0xffffffffu, bidx, o);
            if (ob < best || (ob == best && oi < bidx)) { best = ob; bidx = oi; }
        }
        float zl = z[lane];
        float zq = scbT[lane * NC + bidx];
        float st = zl + (zq - zl);
        zq1[row * LAT + lane] = st;
        zq2[row * LAT + lane] = st;
        float df = zl - zq;
        float ps = df * df;
#pragma unroll
        for (int o = 16; o; o >>= 1) ps += __shfl_xor_sync(0xffffffffu, ps, o);
        if (lane == 0) {
            wsum += ps;
            idx_out[row] = (float)bidx;
        }
    }
    if (lane == 0) swsum[warp] = wsum;
    __syncthreads();
    if (tid == 0) {
        float t = 0.f;
        for (int wq = 0; wq < 8; wq++) t += swsum[wq];
        part[blockIdx.x] = t;
    }
}

__global__ void loss_reduce(const float* __restrict__ part, float* __restrict__ out)
{
    __shared__ float s[1024];
    int tid = threadIdx.x;
    float a = 0.f;
    for (int i = tid; i < Bsz / 32; i += 1024) a += part[i];
    s[tid] = a;
    __syncthreads();
    for (int o = 512; o; o >>= 1) {
        if (tid < o) s[tid] += s[tid + o];
        __syncthreads();
    }
    if (tid == 0) out[0] = s[0] / (float)((size_t)Bsz * LAT);
}

// ---------------- decoder weight prep ----------------
__global__ void tsplitT(const float* __restrict__ W, __nv_bfloat16* __restrict__ Th,
                        __nv_bfloat16* __restrict__ Tl, int K, int N)
{
    int i = blockIdx.x * 256 + threadIdx.x;
    if (i >= K * N) return;
    int n = i / K, k = i - n * K;
    float v = W[(size_t)k * N + n];
    __nv_bfloat16 hb = __float2bfloat16(v);
    Th[i] = hb;
    Tl[i] = __float2bfloat16(v - __bfloat162float(hb));
}

// ============================================================================
// DECODER GEMM — unchanged (at mma-pipe ceiling)
// ============================================================================
#define RST 20

__global__ __launch_bounds__(256, 2)
void mma2(const __nv_bfloat16* __restrict__ Ahg, const __nv_bfloat16* __restrict__ Alg,
          const __nv_bfloat16* __restrict__ Whg, const __nv_bfloat16* __restrict__ Wlg,
          const float* __restrict__ bias, const float* res, float* Cf,
          __nv_bfloat16* Yh, __nv_bfloat16* Yl, int K, int Ntot, int epi)
{
    extern __shared__ __align__(16) uint32_t dsm[];
    const uint32_t sbase = smem_u32(dsm);
    const int tid = threadIdx.x, lane = tid & 31, warp = tid >> 5;
    const int wm = warp >> 2, wn = warp & 3;
    const int q = lane & 3, rr = lane >> 2;
    const size_t row0 = (size_t)blockIdx.y * 128;
    const int n0 = blockIdx.x * 128;

    float acc[4][4][4];
#pragma unroll
    for (int a = 0; a < 4; a++)
#pragma unroll
        for (int b = 0; b < 4; b++)
#pragma unroll
            for (int c = 0; c < 4; c++) acc[a][b][c] = 0.f;

    uint32_t aoff[4], boff[4];
#pragma unroll
    for (int mt = 0; mt < 4; mt++)
        aoff[mt] = (uint32_t)((wm * 64 + mt * 16 + (lane & 15)) * (RST * 4) + (lane >> 4) * 16);
#pragma unroll
    for (int nt = 0; nt < 4; nt++)
        boff[nt] = (uint32_t)((wn * 32 + nt * 8 + (lane & 7)) * (RST * 4) + ((lane >> 3) & 1) * 16);

    auto fill = [&](int kc, int buf) {
        const uint32_t ah_b = sbase + (uint32_t)buf * 10240;
        const uint32_t al_b = sbase + 20480 + (uint32_t)buf * 10240;
        const uint32_t bh_b = sbase + 40960 + (uint32_t)buf * 10240;
        const uint32_t bl_b = sbase + 61440 + (uint32_t)buf * 10240;
#pragma unroll
        for (int i = 0; i < 4; i++) {
            int fid = tid + i * 256;
            int m = fid >> 3, c4 = fid & 3, lo = (fid >> 2) & 1;
            const __nv_bfloat16* s = (lo ? Alg : Ahg) + (row0 + m) * K + kc + c4 * 8;
            CP16((lo ? al_b : ah_b) + (uint32_t)(m * RST + c4 * 4) * 4, s);
        }
#pragma unroll
        for (int i = 0; i < 4; i++) {
            int fid = tid + i * 256;
            int m = fid >> 3, c4 = fid & 3, lo = (fid >> 2) & 1;
            const __nv_bfloat16* s = (lo ? Wlg : Whg) + (size_t)(n0 + m) * K + kc + c4 * 8;
            CP16((lo ? bl_b : bh_b) + (uint32_t)(m * RST + c4 * 4) * 4, s);
        }
    };

    const int nch = K >> 5;
    fill(0, 0);
    CP_COMMIT();
    for (int c = 0; c < nch; c++) {
        if (c + 1 < nch) {
            fill((c + 1) << 5, (c + 1) & 1);
            CP_COMMIT();
            CP_WAIT1();
        } else {
            CP_WAIT0();
        }
        __syncthreads();
        const int buf = c & 1;
        const uint32_t ah_b = sbase + (uint32_t)buf * 10240;
        const uint32_t al_b = sbase + 20480 + (uint32_t)buf * 10240;
        const uint32_t bh_b = sbase + 40960 + (uint32_t)buf * 10240;
        const uint32_t bl_b = sbase + 61440 + (uint32_t)buf * 10240;
#pragma unroll
        for (int ks = 0; ks < 2; ks++) {
            const uint32_t ko = (uint32_t)ks * 32;
            uint32_t ah[4][4], al[4][4], bh[4][2], bl[4][2];
#pragma unroll
            for (int mt = 0; mt < 4; mt++) {
                LDSM_X4(ah[mt][0], ah[mt][1], ah[mt][2], ah[mt][3], ah_b + aoff[mt] + ko);
                LDSM_X4(al[mt][0], al[mt][1], al[mt][2], al[mt][3], al_b + aoff[mt] + ko);
            }
#pragma unroll
            for (int nt = 0; nt < 4; nt++) {
                LDSM_X2(bh[nt][0], bh[nt][1], bh_b + boff[nt] + ko);
                LDSM_X2(bl[nt][0], bl[nt][1], bl_b + boff[nt] + ko);
            }
#pragma unroll
            for (int mt = 0; mt < 4; mt++)
#pragma unroll
                for (int nt = 0; nt < 4; nt++) {
                    mma_bf16(acc[mt][nt], ah[mt], bh[nt]);
                    mma_bf16(acc[mt][nt], ah[mt], bl[nt]);
                    mma_bf16(acc[mt][nt], al[mt], bh[nt]);
                }
        }
        __syncthreads();
    }

#pragma unroll
    for (int mt = 0; mt < 4; mt++) {
        size_t r0 = row0 + wm * 64 + mt * 16 + rr;
        size_t r1 = r0 + 8;
#pragma unroll
        for (int nt = 0; nt < 4; nt++) {
            int gc = n0 + wn * 32 + nt * 8 + q * 2;
            float2 bv = __ldg((const float2*)(bias + gc));
            float v00 = acc[mt][nt][0] + bv.x;
            float v01 = acc[mt][nt][1] + bv.y;
            float v10 = acc[mt][nt][2] + bv.x;
            float v11 = acc[mt][nt][3] + bv.y;
            if (epi == 1) {
                v00 = gelu_erf(v00); v01 = gelu_erf(v01);
                v10 = gelu_erf(v10); v11 = gelu_erf(v11);
                uint32_t h0, l0, h1, l1;
                bsplit2(v00, v01, h0, l0);
                bsplit2(v10, v11, h1, l1);
                *(uint32_t*)(Yh + r0 * Ntot + gc) = h0;
                *(uint32_t*)(Yl + r0 * Ntot + gc) = l0;
                *(uint32_t*)(Yh + r1 * Ntot + gc) = h1;
                *(uint32_t*)(Yl + r1 * Ntot + gc) = l1;
            } else {
                float2 rv0 = *(const float2*)(res + r0 * Ntot + gc);
                float2 rv1 = *(const float2*)(res + r1 * Ntot + gc);
                v00 += rv0.x; v01 += rv0.y; v10 += rv1.x; v11 += rv1.y;
                *(float2*)(Cf + r0 * Ntot + gc) = make_float2(v00, v01);
                *(float2*)(Cf + r1 * Ntot + gc) = make_float2(v10, v11);
            }
        }
    }
}

// ---------------- orchestration ----------------
extern "C" void kernel_launch(void* const* d_in, const int* in_sizes, int n_in,
                              void* d_out, int out_size)
{
    const float* x    = (const float*)d_in[0];
    const float* epw  = (const float*)d_in[1];
    const float* epb  = (const float*)d_in[2];
    const float* elng = (const float*)d_in[3];
    const float* elnb = (const float*)d_in[4];
    const float* ew1  = (const float*)d_in[5];
    const float* eb1  = (const float*)d_in[6];
    const float* ew2  = (const float*)d_in[7];
    const float* eb2  = (const float*)d_in[8];
    const float* eng  = (const float*)d_in[9];
    const float* enb  = (const float*)d_in[10];
    const float* elw  = (const float*)d_in[11];
    const float* elb  = (const float*)d_in[12];
    const float* cb   = (const float*)d_in[13];
    const float* dlw  = (const float*)d_in[14];
    const float* dlb  = (const float*)d_in[15];
    const float* dlng = (const float*)d_in[16];
    const float* dlnb = (const float*)d_in[17];
    const float* dw1  = (const float*)d_in[18];
    const float* db1  = (const float*)d_in[19];
    const float* dw2  = (const float*)d_in[20];
    const float* db2  = (const float*)d_in[21];
    const float* dng  = (const float*)d_in[22];
    const float* dnb  = (const float*)d_in[23];
    const float* dpw  = (const float*)d_in[24];
    const float* dpb  = (const float*)d_in[25];

    float* out = (float*)d_out;
    float* o_xrec = out;
    float* o_zq   = out + (size_t)Bsz * IN_D;
    float* o_idx  = o_zq + (size_t)Bsz * LAT;
    float* o_loss = o_idx + (size_t)Bsz;

    float *h, *y, *z, *zq, *part, *stats;
    __nv_bfloat16 *wh16, *wl16, *ah16, *al16;
    cudaGetSymbolAddress((void**)&h, g_h);
    cudaGetSymbolAddress((void**)&y, g_y);
    cudaGetSymbolAddress((void**)&z, g_z);
    cudaGetSymbolAddress((void**)&zq, g_zq);
    cudaGetSymbolAddress((void**)&part, g_part);
    cudaGetSymbolAddress((void**)&stats, g_stats);
    cudaGetSymbolAddress((void**)&wh16, g_wh16);
    cudaGetSymbolAddress((void**)&wl16, g_wl16);
    cudaGetSymbolAddress((void**)&ah16, g_ah16);
    cudaGetSymbolAddress((void**)&al16, g_al16);

    __nv_bfloat16* yh16 = (__nv_bfloat16*)y;
    __nv_bfloat16* yl16 = yh16 + (size_t)Bsz * EXPD;

    const int MMA_SMEM = 81920;
    cudaFuncSetAttribute(mma2, cudaFuncAttributeMaxDynamicSharedMemorySize, MMA_SMEM);
    cudaFuncSetAttribute(vq_kernel, cudaFuncAttributeMaxDynamicSharedMemorySize, 70656);
    const int SM_N256_54 = (54 * 256 + 32 * 54) * 4;
    const int SM_N256_32 = (32 * 256 + 32 * 32) * 4;
    const int SM_LN32    = (256 * 32 + 32 * HST) * 4;   // 66048
    const int SM_LN54    = (256 * 54 + 32 * HST) * 4;   // 88576
    cudaFuncSetAttribute(small_gemm_n256<54>, cudaFuncAttributeMaxDynamicSharedMemorySize, SM_N256_54);
    cudaFuncSetAttribute(small_gemm_n256<32>, cudaFuncAttributeMaxDynamicSharedMemorySize, SM_N256_32);
    cudaFuncSetAttribute(ln_gemm_n32, cudaFuncAttributeMaxDynamicSharedMemorySize, SM_LN32);
    cudaFuncSetAttribute(ln_gemm_n54, cudaFuncAttributeMaxDynamicSharedMemorySize, SM_LN54);

    const size_t WSZ = 131072;
    const size_t OW1D = 0, OW2D = 4 * WSZ;

    // ---- encoder: frozen FFMA2 fp32 path (bit-identical z -> indices) ----
    small_gemm_n256<54><<<Bsz / 32, 256, SM_N256_54>>>(x, epw, epb, h);
    for (int i = 0; i < NB; i++) {
        ln_stats<<<Bsz / 8, 256>>>(h, (float2*)stats);
        gemm128<<<dim3(EXPD / 128, Bsz / 128), 256>>>(
            h, ew1 + (size_t)i * HID * EXPD, eb1 + i * EXPD, nullptr, y, HID, EXPD, 1,
            (const float2*)stats, elng + i * HID, elnb + i * HID);
        gemm128<<<dim3(HID / 128, Bsz / 128), 256>>>(
            y, ew2 + (size_t)i * EXPD * HID, eb2 + i * HID, h, h, EXPD, HID, 2,
            nullptr, nullptr, nullptr);
    }
    // fused final LN + z projection (hn never touches HBM)
    ln_gemm_n32<<<Bsz / 32, 256, SM_LN32>>>(h, eng, enb, elw, elb, z);

    // ---- VQ ----
    vq_kernel<<<Bsz / 32, 256, (NC * LAT + NC) * 4>>>(z, cb, o_idx, o_zq, zq, part);
    loss_reduce<<<1, 1024>>>(part, o_loss);

    // ---- decoder weight prep ----
    for (int i = 0; i < NB; i++) {
        tsplitT<<<512, 256>>>(dw1 + i * WSZ, wh16 + OW1D + i * WSZ, wl16 + OW1D + i * WSZ, HID, EXPD);
        tsplitT<<<512, 256>>>(dw2 + i * WSZ, wh16 + OW2D + i * WSZ, wl16 + OW2D + i * WSZ, EXPD, HID);
    }

    // ---- decoder: bf16 split mma pipeline ----
    small_gemm_n256<32><<<Bsz / 32, 256, SM_N256_32>>>(zq, dlw, dlb, h);
    for (int i = 0; i < NB; i++) {
        ln_split<<<Bsz / 8, 256>>>(h, dlng + i * HID, dlnb + i * HID, ah16, al16);
        mma2<<<dim3(EXPD / 128, Bsz / 128), 256, MMA_SMEM>>>(
            ah16, al16, wh16 + OW1D + i * WSZ, wl16 + OW1D + i * WSZ, db1 + i * EXPD,
            nullptr, nullptr, yh16, yl16, HID, EXPD, 1);
        mma2<<<dim3(HID / 128, Bsz / 128), 256, MMA_SMEM>>>(
            yh16, yl16, wh16 + OW2D + i * WSZ, wl16 + OW2D + i * WSZ, db2 + i * HID,
            h, h, nullptr, nullptr, EXPD, HID, 2);
    }
    // fused final LN + output projection
    ln_gemm_n54<<<Bsz / 32, 256, SM_LN54>>>(h, dng, dnb, dpw, dpb, o_xrec);
}

// round 17
// speedup vs baseline: 1.1507x; 1.0137x over previous
#include <cuda_runtime.h>
#include <cuda_bf16.h>
#include <math.h>
#include <stdint.h>

#define Bsz 262144
#define IN_D 54
#define HID 256
#define EXPD 512
#define LAT 32
#define NB 4
#define NC 512
#define EPSL 1e-5f

// ---------------- scratch (device globals: allocation-free) ----------------
__device__ float g_h [(size_t)Bsz * HID];
__device__ float g_y [(size_t)Bsz * EXPD];
__device__ float g_z [(size_t)Bsz * LAT];
__device__ float g_zq[(size_t)Bsz * LAT];
__device__ float g_part[Bsz / 64];
__device__ float g_stats[(size_t)Bsz * 2];
__device__ __nv_bfloat16 g_wh16[1048576];
__device__ __nv_bfloat16 g_wl16[1048576];
__device__ __nv_bfloat16 g_ah16[(size_t)Bsz * HID];
__device__ __nv_bfloat16 g_al16[(size_t)Bsz * HID];

// ---------------- helpers ----------------
__device__ __forceinline__ uint32_t smem_u32(const void* p) {
    uint32_t a;
    asm("{ .reg .u64 t; cvta.to.shared.u64 t, %1; cvt.u32.u64 %0, t; }" : "=r"(a) : "l"(p));
    return a;
}
__device__ __forceinline__ float gelu_erf(float v) {
    return 0.5f * v * (1.0f + erff(v * 0.70710678118654752f));
}
__device__ __forceinline__ void mma_bf16(float* c, const uint32_t* a, const uint32_t* b) {
    asm volatile(
        "mma.sync.aligned.m16n8k16.row.col.f32.bf16.bf16.f32 "
        "{%0,%1,%2,%3}, {%4,%5,%6,%7}, {%8,%9}, {%0,%1,%2,%3};"
        : "+f"(c[0]), "+f"(c[1]), "+f"(c[2]), "+f"(c[3])
        : "r"(a[0]), "r"(a[1]), "r"(a[2]), "r"(a[3]), "r"(b[0]), "r"(b[1]));
}
__device__ __forceinline__ void bsplit2(float vx, float vy, uint32_t& hw, uint32_t& lw) {
    __nv_bfloat16 hx = __float2bfloat16(vx);
    __nv_bfloat16 hy = __float2bfloat16(vy);
    __nv_bfloat16 lx = __float2bfloat16(vx - __bfloat162float(hx));
    __nv_bfloat16 ly = __float2bfloat16(vy - __bfloat162float(hy));
    __nv_bfloat162 hp; hp.x = hx; hp.y = hy;
    __nv_bfloat162 lp; lp.x = lx; lp.y = ly;
    hw = *(uint32_t*)&hp;
    lw = *(uint32_t*)&lp;
}

#define FFMA2(accp, ap, bp) \
    asm volatile("fma.rn.f32x2 %0, %1, %2, %0;" : "+l"(accp) : "l"(ap), "l"(bp))
#define PACK_DUP(dst, s) \
    asm("mov.b64 %0, {%1, %1};" : "=l"(dst) : "f"(s))
#define UNPACK2(lo, hi, src) \
    asm("mov.b64 {%0, %1}, %2;" : "=f"(lo), "=f"(hi) : "l"(src))

#define CP16(dst, src) \
    asm volatile("cp.async.cg.shared.global [%0], [%1], 16;" :: "r"(dst), "l"(src) : "memory")
#define CP_COMMIT() asm volatile("cp.async.commit_group;" ::: "memory")
#define CP_WAIT0()  asm volatile("cp.async.wait_group 0;" ::: "memory")
#define CP_WAIT1()  asm volatile("cp.async.wait_group 1;" ::: "memory")

#define LDSM_X4(r0, r1, r2, r3, addr) \
    asm volatile("ldmatrix.sync.aligned.m8n8.x4.shared.b16 {%0,%1,%2,%3}, [%4];" \
        : "=r"(r0), "=r"(r1), "=r"(r2), "=r"(r3) : "r"(addr))
#define LDSM_X2(r0, r1, addr) \
    asm volatile("ldmatrix.sync.aligned.m8n8.x2.shared.b16 {%0,%1}, [%2];" \
        : "=r"(r0), "=r"(r1) : "r"(addr))

#define AKEY(k) (((((k) & 12) >> 2)) | (((k) & 3) << 2))
#define BPRM(s) ((s) ^ (((s) >> 3) & 1))

// ============================================================================
// ENCODER fp32 GEMM — FFMA2 (byte-identical to round 13/15/16: bit-exact)
// ============================================================================
__global__ __launch_bounds__(256, 2)
void gemm128(const float* __restrict__ A, const float* __restrict__ W,
             const float* __restrict__ bias, const float* __restrict__ res,
             float* __restrict__ C, int K, int N, int epi,
             const float2* __restrict__ stats,
             const float* __restrict__ lng, const float* __restrict__ lnb)
{
    __shared__ __align__(16) float As[2][2048];
    __shared__ __align__(16) float Ws[2][2048];

    const int tid = threadIdx.x;
    const int tx = tid & 15, ty = tid >> 4;
    const size_t row0 = (size_t)blockIdx.y * 128;
    const int col0 = blockIdx.x * 128;

    const int ar0 = tid >> 2, ar1 = ar0 + 64;
    const int ac  = (tid & 3) * 4;
    const int wr0 = tid >> 5, wr1 = wr0 + 8;
    const int ws  = tid & 31;
    const int wsw = BPRM(ws) * 4;
    const int wc  = ws * 4;

    const uint32_t wbase = smem_u32(Ws);

    float2 st0, st1;
    if (stats) {
        st0 = __ldg(stats + row0 + ar0);
        st1 = __ldg(stats + row0 + ar1);
    }

    unsigned long long acc2[8][4];
#pragma unroll
    for (int i = 0; i < 8; i++)
#pragma unroll
        for (int j = 0; j < 4; j++) acc2[i][j] = 0ULL;

    const int bo0 = BPRM(tx * 2) * 4;
    const int bo1 = BPRM(tx * 2 + 1) * 4;

    const int nch = K >> 4;
    float4 av0, av1;

    CP16(wbase + (uint32_t)(0 * 2048 + wr0 * 128 + wsw) * 4, W + (size_t)wr0 * N + col0 + wc);
    CP16(wbase + (uint32_t)(0 * 2048 + wr1 * 128 + wsw) * 4, W + (size_t)wr1 * N + col0 + wc);
    CP_COMMIT();
    av0 = *(const float4*)(A + (row0 + ar0) * K + ac);
    av1 = *(const float4*)(A + (row0 + ar1) * K + ac);
    if (stats) {
        av0.x = fmaf((av0.x - st0.x) * st0.y, __ldg(lng + ac + 0), __ldg(lnb + ac + 0));
        av0.y = fmaf((av0.y - st0.x) * st0.y, __ldg(lng + ac + 1), __ldg(lnb + ac + 1));
        av0.z = fmaf((av0.z - st0.x) * st0.y, __ldg(lng + ac + 2), __ldg(lnb + ac + 2));
        av0.w = fmaf((av0.w - st0.x) * st0.y, __ldg(lng + ac + 3), __ldg(lnb + ac + 3));
        av1.x = fmaf((av1.x - st1.x) * st1.y, __ldg(lng + ac + 0), __ldg(lnb + ac + 0));
        av1.y = fmaf((av1.y - st1.x) * st1.y, __ldg(lng + ac + 1), __ldg(lnb + ac + 1));
        av1.z = fmaf((av1.z - st1.x) * st1.y, __ldg(lng + ac + 2), __ldg(lnb + ac + 2));
        av1.w = fmaf((av1.w - st1.x) * st1.y, __ldg(lng + ac + 3), __ldg(lnb + ac + 3));
    }
    {
        float v0[4] = {av0.x, av0.y, av0.z, av0.w};
        float v1[4] = {av1.x, av1.y, av1.z, av1.w};
#pragma unroll
        for (int j = 0; j < 4; j++) {
            int kidx = ac + j;
            As[0][kidx * 128 + ((((ar0 >> 2) ^ AKEY(kidx)) << 2) | (ar0 & 3))] = v0[j];
            As[0][kidx * 128 + ((((ar1 >> 2) ^ AKEY(kidx)) << 2) | (ar1 & 3))] = v1[j];
        }
    }
    CP_WAIT0();
    __syncthreads();

    for (int c = 0; c < nch; c++) {
        const int buf = c & 1;
        if (c + 1 < nch) {
            const int kk = (c + 1) << 4;
            CP16(wbase + (uint32_t)((buf ^ 1) * 2048 + wr0 * 128 + wsw) * 4,
                 W + (size_t)(kk + wr0) * N + col0 + wc);
            CP16(wbase + (uint32_t)((buf ^ 1) * 2048 + wr1 * 128 + wsw) * 4,
                 W + (size_t)(kk + wr1) * N + col0 + wc);
            CP_COMMIT();
            av0 = *(const float4*)(A + (row0 + ar0) * K + kk + ac);
            av1 = *(const float4*)(A + (row0 + ar1) * K + kk + ac);
        }
#pragma unroll
        for (int k = 0; k < 16; k++) {
            float a[8];
            *(float4*)&a[0] = *(const float4*)&As[buf][k * 128 + (((ty * 2)     ^ AKEY(k)) << 2)];
            *(float4*)&a[4] = *(const float4*)&As[buf][k * 128 + (((ty * 2 + 1) ^ AKEY(k)) << 2)];
            ulonglong2 vb0 = *(const ulonglong2*)&Ws[buf][k * 128 + bo0];
            ulonglong2 vb1 = *(const ulonglong2*)&Ws[buf][k * 128 + bo1];
            unsigned long long b2[4] = {vb0.x, vb0.y, vb1.x, vb1.y};
            unsigned long long a2[8];
#pragma unroll
            for (int i = 0; i < 8; i++) PACK_DUP(a2[i], a[i]);
#pragma unroll
            for (int i = 0; i < 8; i++)
#pragma unroll
                for (int j = 0; j < 4; j++)
                    FFMA2(acc2[i][j], a2[i], b2[j]);
        }
        if (c + 1 < nch) {
            const int kk = (c + 1) << 4;
            if (stats) {
                av0.x = fmaf((av0.x - st0.x) * st0.y, __ldg(lng + kk + ac + 0), __ldg(lnb + kk + ac + 0));
                av0.y = fmaf((av0.y - st0.x) * st0.y, __ldg(lng + kk + ac + 1), __ldg(lnb + kk + ac + 1));
                av0.z = fmaf((av0.z - st0.x) * st0.y, __ldg(lng + kk + ac + 2), __ldg(lnb + kk + ac + 2));
                av0.w = fmaf((av0.w - st0.x) * st0.y, __ldg(lng + kk + ac + 3), __ldg(lnb + kk + ac + 3));
                av1.x = fmaf((av1.x - st1.x) * st1.y, __ldg(lng + kk + ac + 0), __ldg(lnb + kk + ac + 0));
                av1.y = fmaf((av1.y - st1.x) * st1.y, __ldg(lng + kk + ac + 1), __ldg(lnb + kk + ac + 1));
                av1.z = fmaf((av1.z - st1.x) * st1.y, __ldg(lng + kk + ac + 2), __ldg(lnb + kk + ac + 2));
                av1.w = fmaf((av1.w - st1.x) * st1.y, __ldg(lng + kk + ac + 3), __ldg(lnb + kk + ac + 3));
            }
            float v0[4] = {av0.x, av0.y, av0.z, av0.w};
            float v1[4] = {av1.x, av1.y, av1.z, av1.w};
#pragma unroll
            for (int j = 0; j < 4; j++) {
                int kidx = ac + j;
                As[buf ^ 1][kidx * 128 + ((((ar0 >> 2) ^ AKEY(kidx)) << 2) | (ar0 & 3))] = v0[j];
                As[buf ^ 1][kidx * 128 + ((((ar1 >> 2) ^ AKEY(kidx)) << 2) | (ar1 & 3))] = v1[j];
            }
            CP_WAIT0();
        }
        __syncthreads();
    }

#pragma unroll
    for (int i = 0; i < 8; i++) {
        size_t r = row0 + ty * 8 + i;
#pragma unroll
        for (int jc = 0; jc < 4; jc++) {
            float e0, e1;
            UNPACK2(e0, e1, acc2[i][jc]);
            int cix = col0 + tx * 8 + jc * 2;
            float2 bv = __ldg((const float2*)(bias + cix));
            float v0 = e0 + bv.x;
            float v1 = e1 + bv.y;
            if (epi == 1) {
                v0 = 0.5f * v0 * (1.0f + erff(v0 * 0.70710678118654752f));
                v1 = 0.5f * v1 * (1.0f + erff(v1 * 0.70710678118654752f));
            } else if (epi == 2) {
                float2 rv = *(const float2*)(res + r * N + cix);
                v0 += rv.x;
                v1 += rv.y;
            }
            *(float2*)(C + r * N + cix) = make_float2(v0, v1);
        }
    }
}

// ---------------- per-row layernorm stats (encoder) ----------------
__global__ void ln_stats(const float* __restrict__ H, float2* __restrict__ st)
{
    int gw = (int)((blockIdx.x * blockDim.x + threadIdx.x) >> 5);
    int lane = threadIdx.x & 31;
    const float* h = H + (size_t)gw * HID + lane * 8;
    float4 v0 = *(const float4*)h;
    float4 v1 = *(const float4*)(h + 4);
    float v[8] = {v0.x, v0.y, v0.z, v0.w, v1.x, v1.y, v1.z, v1.w};
    float s = 0.f;
#pragma unroll
    for (int k = 0; k < 8; k++) s += v[k];
#pragma unroll
    for (int o = 16; o; o >>= 1) s += __shfl_xor_sync(0xffffffffu, s, o);
    float mu = s * (1.0f / HID);
    float q = 0.f;
#pragma unroll
    for (int k = 0; k < 8; k++) { float d = v[k] - mu; q = fmaf(d, d, q); }
#pragma unroll
    for (int o = 16; o; o >>= 1) q += __shfl_xor_sync(0xffffffffu, q, o);
    float w = rsqrtf(q * (1.0f / HID) + EPSL);
    if (lane == 0) st[gw] = make_float2(mu, w);
}

// ---------------- layernorm + bf16 hi/lo split (decoder) ----------------
__global__ void ln_split(const float* __restrict__ H, const float* __restrict__ g,
                         const float* __restrict__ b,
                         __nv_bfloat16* __restrict__ Oh, __nv_bfloat16* __restrict__ Ol)
{
    int gw = (int)((blockIdx.x * blockDim.x + threadIdx.x) >> 5);
    int lane = threadIdx.x & 31;
    const float* h = H + (size_t)gw * HID + lane * 8;
    float4 v0 = *(const float4*)h;
    float4 v1 = *(const float4*)(h + 4);
    float v[8] = {v0.x, v0.y, v0.z, v0.w, v1.x, v1.y, v1.z, v1.w};
    float s = 0.f;
#pragma unroll
    for (int k = 0; k < 8; k++) s += v[k];
#pragma unroll
    for (int o = 16; o; o >>= 1) s += __shfl_xor_sync(0xffffffffu, s, o);
    float mu = s * (1.0f / HID);
    float d[8], q = 0.f;
#pragma unroll
    for (int k = 0; k < 8; k++) { d[k] = v[k] - mu; q = fmaf(d[k], d[k], q); }
#pragma unroll
    for (int o = 16; o; o >>= 1) q += __shfl_xor_sync(0xffffffffu, q, o);
    float w = rsqrtf(q * (1.0f / HID) + EPSL);
    const float* gg = g + lane * 8;
    const float* bb = b + lane * 8;
    uint32_t wh[4], wl[4];
#pragma unroll
    for (int p = 0; p < 4; p++) {
        float oa = fmaf(d[2 * p] * w, __ldg(gg + 2 * p), __ldg(bb + 2 * p));
        float ob = fmaf(d[2 * p + 1] * w, __ldg(gg + 2 * p + 1), __ldg(bb + 2 * p + 1));
        bsplit2(oa, ob, wh[p], wl[p]);
    }
    *(uint4*)(Oh + (size_t)gw * HID + lane * 8) = make_uint4(wh[0], wh[1], wh[2], wh[3]);
    *(uint4*)(Ol + (size_t)gw * HID + lane * 8) = make_uint4(wl[0], wl[1], wl[2], wl[3]);
}

// ---------------- small GEMM N=256 (enc_proj / dec in-proj) ----------------
template <int K>
__global__ __launch_bounds__(256)
void small_gemm_n256(const float* __restrict__ A, const float* __restrict__ W,
                     const float* __restrict__ bias, float* __restrict__ C)
{
    extern __shared__ float smx[];
    float* sW = smx;
    float* sAT = smx + K * 256;
    const int tid = threadIdx.x;
    const size_t row0 = (size_t)blockIdx.x * 32;
    for (int i = tid; i < K * 256; i += 256) {
        int k = i >> 8, c = i & 255;
        sW[k * 256 + (c ^ ((c >> 5) << 2))] = W[i];
    }
    for (int i = tid; i < 32 * K; i += 256) {
        int r = i / K, k = i - r * K;
        sAT[k * 32 + r] = A[(row0 + r) * K + k];
    }
    __syncthreads();
    const int r = tid >> 3;
    const int qq = tid & 7;
    const int c0 = qq * 32;
    float acc[32];
#pragma unroll
    for (int t = 0; t < 32; t++) acc[t] = 0.f;
#pragma unroll
    for (int k = 0; k < K; k++) {
        float a = sAT[k * 32 + r];
        const float* wrow = sW + k * 256;
#pragma unroll
        for (int j = 0; j < 8; j++) {
            float4 w4 = *(const float4*)(wrow + ((c0 + 4 * j) ^ (qq << 2)));
            acc[4 * j + 0] = fmaf(a, w4.x, acc[4 * j + 0]);
            acc[4 * j + 1] = fmaf(a, w4.y, acc[4 * j + 1]);
            acc[4 * j + 2] = fmaf(a, w4.z, acc[4 * j + 2]);
            acc[4 * j + 3] = fmaf(a, w4.w, acc[4 * j + 3]);
        }
    }
    float* cp = C + (row0 + r) * 256 + c0;
#pragma unroll
    for (int t = 0; t < 32; t++) cp[t] = acc[t] + __ldg(bias + c0 + t);
}

// ============================================================================
// FUSED final-LN + projection kernels (round-16, bit-exact)
// ============================================================================
#define HST 260

__global__ __launch_bounds__(256)
void ln_gemm_n32(const float* __restrict__ H, const float* __restrict__ g,
                 const float* __restrict__ b, const float* __restrict__ W,
                 const float* __restrict__ bias, float* __restrict__ C)
{
    extern __shared__ float smx[];
    float* sW = smx;
    float* sA = smx + 256 * 32;
    const int tid = threadIdx.x;
    const int warp = tid >> 5, lane = tid & 31;
    const size_t row0 = (size_t)blockIdx.x * 32;
    for (int i = tid; i < 256 * 32; i += 256) sW[i] = W[i];
#pragma unroll 1
    for (int rr = 0; rr < 4; rr++) {
        int r = warp * 4 + rr;
        const float* h = H + (row0 + r) * HID + lane * 8;
        float4 v0 = *(const float4*)h;
        float4 v1 = *(const float4*)(h + 4);
        float v[8] = {v0.x, v0.y, v0.z, v0.w, v1.x, v1.y, v1.z, v1.w};
        float s = 0.f;
#pragma unroll
        for (int k = 0; k < 8; k++) s += v[k];
#pragma unroll
        for (int o = 16; o; o >>= 1) s += __shfl_xor_sync(0xffffffffu, s, o);
        float mu = s * (1.0f / HID);
        float d[8], q = 0.f;
#pragma unroll
        for (int k = 0; k < 8; k++) { d[k] = v[k] - mu; q = fmaf(d[k], d[k], q); }
#pragma unroll
        for (int o = 16; o; o >>= 1) q += __shfl_xor_sync(0xffffffffu, q, o);
        float w = rsqrtf(q * (1.0f / HID) + EPSL);
        const float* gg = g + lane * 8;
        const float* bb = b + lane * 8;
        float o8[8];
#pragma unroll
        for (int k = 0; k < 8; k++) o8[k] = fmaf(d[k] * w, __ldg(gg + k), __ldg(bb + k));
        float* dst = sA + r * HST + lane * 8;
        *(float4*)dst = make_float4(o8[0], o8[1], o8[2], o8[3]);
        *(float4*)(dst + 4) = make_float4(o8[4], o8[5], o8[6], o8[7]);
    }
    __syncthreads();
    const int r = tid >> 3;
    const int c0 = (tid & 7) * 4;
    float acc[4] = {0.f, 0.f, 0.f, 0.f};
#pragma unroll
    for (int k = 0; k < 256; k++) {
        float a = sA[r * HST + k];
        const float* wr = sW + k * 32 + c0;
#pragma unroll
        for (int t = 0; t < 4; t++) acc[t] = fmaf(a, wr[t], acc[t]);
    }
    float* cp = C + (row0 + r) * 32 + c0;
#pragma unroll
    for (int t = 0; t < 4; t++) cp[t] = acc[t] + __ldg(bias + c0 + t);
}

__global__ __launch_bounds__(256)
void ln_gemm_n54(const float* __restrict__ H, const float* __restrict__ g,
                 const float* __restrict__ b, const float* __restrict__ W,
                 const float* __restrict__ bias, float* __restrict__ C)
{
    extern __shared__ float smx[];
    float* sW = smx;
    float* sA = smx + 256 * 54;
    const int tid = threadIdx.x;
    const int warp = tid >> 5, lane = tid & 31;
    const size_t row0 = (size_t)blockIdx.x * 32;
    for (int i = tid; i < 256 * 54; i += 256) sW[i] = W[i];
#pragma unroll 1
    for (int rr = 0; rr < 4; rr++) {
        int r = warp * 4 + rr;
        const float* h = H + (row0 + r) * HID + lane * 8;
        float4 v0 = *(const float4*)h;
        float4 v1 = *(const float4*)(h + 4);
        float v[8] = {v0.x, v0.y, v0.z, v0.w, v1.x, v1.y, v1.z, v1.w};
        float s = 0.f;
#pragma unroll
        for (int k = 0; k < 8; k++) s += v[k];
#pragma unroll
        for (int o = 16; o; o >>= 1) s += __shfl_xor_sync(0xffffffffu, s, o);
        float mu = s * (1.0f / HID);
        float d[8], q = 0.f;
#pragma unroll
        for (int k = 0; k < 8; k++) { d[k] = v[k] - mu; q = fmaf(d[k], d[k], q); }
#pragma unroll
        for (int o = 16; o; o >>= 1) q += __shfl_xor_sync(0xffffffffu, q, o);
        float w = rsqrtf(q * (1.0f / HID) + EPSL);
        const float* gg = g + lane * 8;
        const float* bb = b + lane * 8;
        float o8[8];
#pragma unroll
        for (int k = 0; k < 8; k++) o8[k] = fmaf(d[k] * w, __ldg(gg + k), __ldg(bb + k));
        float* dst = sA + r * HST + lane * 8;
        *(float4*)dst = make_float4(o8[0], o8[1], o8[2], o8[3]);
        *(float4*)(dst + 4) = make_float4(o8[4], o8[5], o8[6], o8[7]);
    }
    __syncthreads();
    const int r = tid >> 3;
    const int c0 = (tid & 7) * 7;
    float acc[7] = {0.f, 0.f, 0.f, 0.f, 0.f, 0.f, 0.f};
#pragma unroll
    for (int k = 0; k < 256; k++) {
        float a = sA[r * HST + k];
        const float* wr = sW + k * 54 + c0;
#pragma unroll
        for (int t = 0; t < 7; t++)
            if (c0 + t < 54) acc[t] = fmaf(a, wr[t], acc[t]);
    }
    float* cp = C + (row0 + r) * 54 + c0;
#pragma unroll
    for (int t = 0; t < 7; t++)
        if (c0 + t < 54) cp[t] = acc[t] + __ldg(bias + c0 + t);
}

// ---------------- VQ: 8 rows per warp (bit-exact indices) ------------------
__global__ void vq_kernel(const float* __restrict__ Z, const float* __restrict__ CB,
                          float* __restrict__ idx_out, float* __restrict__ zq1,
                          float* __restrict__ zq2, float* __restrict__ part)
{
    extern __shared__ float smx[];
    float* scbT = smx;
    float* sn2 = smx + NC * LAT;
    __shared__ float swsum[8];
    int tid = threadIdx.x;
    for (int i = tid; i < NC * LAT; i += 256) {
        int c = i & (NC - 1);
        int j = i >> 9;
        scbT[j * NC + c] = CB[(size_t)c * LAT + j];
    }
    __syncthreads();
    for (int c = tid; c < NC; c += 256) {
        float s = 0.f;
#pragma unroll
        for (int j = 0; j < LAT; j++) { float t = scbT[j * NC + c]; s = fmaf(t, t, s); }
        sn2[c] = s;
    }
    __syncthreads();

    int warp = tid >> 5, lane = tid & 31;
    float wsum = 0.f;
#pragma unroll 1
    for (int rr8 = 0; rr8 < 8; rr8++) {
        size_t row = (size_t)blockIdx.x * 64 + warp * 8 + rr8;
        const float* z = Z + row * LAT;
        float zv[LAT];
#pragma unroll
        for (int j = 0; j < LAT; j++) zv[j] = z[j];

        float best = 3.4e38f;
        int bidx = 0;
        for (int c = lane; c < NC; c += 32) {
            float s = 0.f;
#pragma unroll
            for (int j = 0; j < LAT; j++) s = fmaf(zv[j], scbT[j * NC + c], s);
            float d2 = sn2[c] - 2.f * s;
            if (d2 < best) { best = d2; bidx = c; }
        }
#pragma unroll
        for (int o = 16; o; o >>= 1) {
            float ob = __shfl_xor_sync(0xffffffffu, best, o);
            int oi = __shfl_xor_sync(0xffffffffu, bidx, o);
            if (ob < best || (ob == best && oi < bidx)) { best = ob; bidx = oi; }
        }
        float zl = z[lane];
        float zq = scbT[lane * NC + bidx];
        float st = zl + (zq - zl);
        zq1[row * LAT + lane] = st;
        zq2[row * LAT + lane] = st;
        float df = zl - zq;
        float ps = df * df;
#pragma unroll
        for (int o = 16; o; o >>= 1) ps += __shfl_xor_sync(0xffffffffu, ps, o);
        if (lane == 0) {
            wsum += ps;
            idx_out[row] = (float)bidx;
        }
    }
    if (lane == 0) swsum[warp] = wsum;
    __syncthreads();
    if (tid == 0) {
        float t = 0.f;
        for (int wq = 0; wq < 8; wq++) t += swsum[wq];
        part[blockIdx.x] = t;
    }
}

__global__ void loss_reduce(const float* __restrict__ part, float* __restrict__ out)
{
    __shared__ float s[1024];
    int tid = threadIdx.x;
    float a = 0.f;
    for (int i = tid; i < Bsz / 64; i += 1024) a += part[i];
    s[tid] = a;
    __syncthreads();
    for (int o = 512; o; o >>= 1) {
        if (tid < o) s[tid] += s[tid + o];
        __syncthreads();
    }
    if (tid == 0) out[0] = s[0] / (float)((size_t)Bsz * LAT);
}

// ---------------- decoder weight prep: all 8 blocks in one launch ----------
__global__ void tsplit8(const float* __restrict__ DW1, const float* __restrict__ DW2,
                        __nv_bfloat16* __restrict__ Th, __nv_bfloat16* __restrict__ Tl)
{
    const int WSZi = 131072;
    int i = blockIdx.x * 256 + threadIdx.x;   // [0, 8*WSZ)
    int blk = i / WSZi;
    int j = i - blk * WSZi;
    float v;
    if (blk < 4) {
        // dw1 block blk: [HID, EXPD] -> transposed [n][k]
        int n = j / HID, k = j - n * HID;
        v = DW1[(size_t)blk * WSZi + (size_t)k * EXPD + n];
    } else {
        // dw2 block blk-4: [EXPD, HID] -> transposed [n][k]
        int n = j / EXPD, k = j - n * EXPD;
        v = DW2[(size_t)(blk - 4) * WSZi + (size_t)k * HID + n];
    }
    __nv_bfloat16 hb = __float2bfloat16(v);
    Th[i] = hb;
    Tl[i] = __float2bfloat16(v - __bfloat162float(hb));
}

// ============================================================================
// DECODER GEMM — unchanged (at mma-pipe ceiling)
// ============================================================================
#define RST 20

__global__ __launch_bounds__(256, 2)
void mma2(const __nv_bfloat16* __restrict__ Ahg, const __nv_bfloat16* __restrict__ Alg,
          const __nv_bfloat16* __restrict__ Whg, const __nv_bfloat16* __restrict__ Wlg,
          const float* __restrict__ bias, const float* res, float* Cf,
          __nv_bfloat16* Yh, __nv_bfloat16* Yl, int K, int Ntot, int epi)
{
    extern __shared__ __align__(16) uint32_t dsm[];
    const uint32_t sbase = smem_u32(dsm);
    const int tid = threadIdx.x, lane = tid & 31, warp = tid >> 5;
    const int wm = warp >> 2, wn = warp & 3;
    const int q = lane & 3, rr = lane >> 2;
    const size_t row0 = (size_t)blockIdx.y * 128;
    const int n0 = blockIdx.x * 128;

    float acc[4][4][4];
#pragma unroll
    for (int a = 0; a < 4; a++)
#pragma unroll
        for (int b = 0; b < 4; b++)
#pragma unroll
            for (int c = 0; c < 4; c++) acc[a][b][c] = 0.f;

    uint32_t aoff[4], boff[4];
#pragma unroll
    for (int mt = 0; mt < 4; mt++)
        aoff[mt] = (uint32_t)((wm * 64 + mt * 16 + (lane & 15)) * (RST * 4) + (lane >> 4) * 16);
#pragma unroll
    for (int nt = 0; nt < 4; nt++)
        boff[nt] = (uint32_t)((wn * 32 + nt * 8 + (lane & 7)) * (RST * 4) + ((lane >> 3) & 1) * 16);

    auto fill = [&](int kc, int buf) {
        const uint32_t ah_b = sbase + (uint32_t)buf * 10240;
        const uint32_t al_b = sbase + 20480 + (uint32_t)buf * 10240;
        const uint32_t bh_b = sbase + 40960 + (uint32_t)buf * 10240;
        const uint32_t bl_b = sbase + 61440 + (uint32_t)buf * 10240;
#pragma unroll
        for (int i = 0; i < 4; i++) {
            int fid = tid + i * 256;
            int m = fid >> 3, c4 = fid & 3, lo = (fid >> 2) & 1;
            const __nv_bfloat16* s = (lo ? Alg : Ahg) + (row0 + m) * K + kc + c4 * 8;
            CP16((lo ? al_b : ah_b) + (uint32_t)(m * RST + c4 * 4) * 4, s);
        }
#pragma unroll
        for (int i = 0; i < 4; i++) {
            int fid = tid + i * 256;
            int m = fid >> 3, c4 = fid & 3, lo = (fid >> 2) & 1;
            const __nv_bfloat16* s = (lo ? Wlg : Whg) + (size_t)(n0 + m) * K + kc + c4 * 8;
            CP16((lo ? bl_b : bh_b) + (uint32_t)(m * RST + c4 * 4) * 4, s);
        }
    };

    const int nch = K >> 5;
    fill(0, 0);
    CP_COMMIT();
    for (int c = 0; c < nch; c++) {
        if (c + 1 < nch) {
            fill((c + 1) << 5, (c + 1) & 1);
            CP_COMMIT();
            CP_WAIT1();
        } else {
            CP_WAIT0();
        }
        __syncthreads();
        const int buf = c & 1;
        const uint32_t ah_b = sbase + (uint32_t)buf * 10240;
        const uint32_t al_b = sbase + 20480 + (uint32_t)buf * 10240;
        const uint32_t bh_b = sbase + 40960 + (uint32_t)buf * 10240;
        const uint32_t bl_b = sbase + 61440 + (uint32_t)buf * 10240;
#pragma unroll
        for (int ks = 0; ks < 2; ks++) {
            const uint32_t ko = (uint32_t)ks * 32;
            uint32_t ah[4][4], al[4][4], bh[4][2], bl[4][2];
#pragma unroll
            for (int mt = 0; mt < 4; mt++) {
                LDSM_X4(ah[mt][0], ah[mt][1], ah[mt][2], ah[mt][3], ah_b + aoff[mt] + ko);
                LDSM_X4(al[mt][0], al[mt][1], al[mt][2], al[mt][3], al_b + aoff[mt] + ko);
            }
#pragma unroll
            for (int nt = 0; nt < 4; nt++) {
                LDSM_X2(bh[nt][0], bh[nt][1], bh_b + boff[nt] + ko);
                LDSM_X2(bl[nt][0], bl[nt][1], bl_b + boff[nt] + ko);
            }
#pragma unroll
            for (int mt = 0; mt < 4; mt++)
#pragma unroll
                for (int nt = 0; nt < 4; nt++) {
                    mma_bf16(acc[mt][nt], ah[mt], bh[nt]);
                    mma_bf16(acc[mt][nt], ah[mt], bl[nt]);
                    mma_bf16(acc[mt][nt], al[mt], bh[nt]);
                }
        }
        __syncthreads();
    }

#pragma unroll
    for (int mt = 0; mt < 4; mt++) {
        size_t r0 = row0 + wm * 64 + mt * 16 + rr;
        size_t r1 = r0 + 8;
#pragma unroll
        for (int nt = 0; nt < 4; nt++) {
            int gc = n0 + wn * 32 + nt * 8 + q * 2;
            float2 bv = __ldg((const float2*)(bias + gc));
            float v00 = acc[mt][nt][0] + bv.x;
            float v01 = acc[mt][nt][1] + bv.y;
            float v10 = acc[mt][nt][2] + bv.x;
            float v11 = acc[mt][nt][3] + bv.y;
            if (epi == 1) {
                v00 = gelu_erf(v00); v01 = gelu_erf(v01);
                v10 = gelu_erf(v10); v11 = gelu_erf(v11);
                uint32_t h0, l0, h1, l1;
                bsplit2(v00, v01, h0, l0);
                bsplit2(v10, v11, h1, l1);
                *(uint32_t*)(Yh + r0 * Ntot + gc) = h0;
                *(uint32_t*)(Yl + r0 * Ntot + gc) = l0;
                *(uint32_t*)(Yh + r1 * Ntot + gc) = h1;
                *(uint32_t*)(Yl + r1 * Ntot + gc) = l1;
            } else {
                float2 rv0 = *(const float2*)(res + r0 * Ntot + gc);
                float2 rv1 = *(const float2*)(res + r1 * Ntot + gc);
                v00 += rv0.x; v01 += rv0.y; v10 += rv1.x; v11 += rv1.y;
                *(float2*)(Cf + r0 * Ntot + gc) = make_float2(v00, v01);
                *(float2*)(Cf + r1 * Ntot + gc) = make_float2(v10, v11);
            }
        }
    }
}

// ---------------- orchestration ----------------
extern "C" void kernel_launch(void* const* d_in, const int* in_sizes, int n_in,
                              void* d_out, int out_size)
{
    const float* x    = (const float*)d_in[0];
    const float* epw  = (const float*)d_in[1];
    const float* epb  = (const float*)d_in[2];
    const float* elng = (const float*)d_in[3];
    const float* elnb = (const float*)d_in[4];
    const float* ew1  = (const float*)d_in[5];
    const float* eb1  = (const float*)d_in[6];
    const float* ew2  = (const float*)d_in[7];
    const float* eb2  = (const float*)d_in[8];
    const float* eng  = (const float*)d_in[9];
    const float* enb  = (const float*)d_in[10];
    const float* elw  = (const float*)d_in[11];
    const float* elb  = (const float*)d_in[12];
    const float* cb   = (const float*)d_in[13];
    const float* dlw  = (const float*)d_in[14];
    const float* dlb  = (const float*)d_in[15];
    const float* dlng = (const float*)d_in[16];
    const float* dlnb = (const float*)d_in[17];
    const float* dw1  = (const float*)d_in[18];
    const float* db1  = (const float*)d_in[19];
    const float* dw2  = (const float*)d_in[20];
    const float* db2  = (const float*)d_in[21];
    const float* dng  = (const float*)d_in[22];
    const float* dnb  = (const float*)d_in[23];
    const float* dpw  = (const float*)d_in[24];
    const float* dpb  = (const float*)d_in[25];

    float* out = (float*)d_out;
    float* o_xrec = out;
    float* o_zq   = out + (size_t)Bsz * IN_D;
    float* o_idx  = o_zq + (size_t)Bsz * LAT;
    float* o_loss = o_idx + (size_t)Bsz;

    float *h, *y, *z, *zq, *part, *stats;
    __nv_bfloat16 *wh16, *wl16, *ah16, *al16;
    cudaGetSymbolAddress((void**)&h, g_h);
    cudaGetSymbolAddress((void**)&y, g_y);
    cudaGetSymbolAddress((void**)&z, g_z);
    cudaGetSymbolAddress((void**)&zq, g_zq);
    cudaGetSymbolAddress((void**)&part, g_part);
    cudaGetSymbolAddress((void**)&stats, g_stats);
    cudaGetSymbolAddress((void**)&wh16, g_wh16);
    cudaGetSymbolAddress((void**)&wl16, g_wl16);
    cudaGetSymbolAddress((void**)&ah16, g_ah16);
    cudaGetSymbolAddress((void**)&al16, g_al16);

    __nv_bfloat16* yh16 = (__nv_bfloat16*)y;
    __nv_bfloat16* yl16 = yh16 + (size_t)Bsz * EXPD;

    const int MMA_SMEM = 81920;
    cudaFuncSetAttribute(mma2, cudaFuncAttributeMaxDynamicSharedMemorySize, MMA_SMEM);
    cudaFuncSetAttribute(vq_kernel, cudaFuncAttributeMaxDynamicSharedMemorySize, 70656);
    const int SM_N256_54 = (54 * 256 + 32 * 54) * 4;
    const int SM_N256_32 = (32 * 256 + 32 * 32) * 4;
    const int SM_LN32    = (256 * 32 + 32 * HST) * 4;
    const int SM_LN54    = (256 * 54 + 32 * HST) * 4;
    cudaFuncSetAttribute(small_gemm_n256<54>, cudaFuncAttributeMaxDynamicSharedMemorySize, SM_N256_54);
    cudaFuncSetAttribute(small_gemm_n256<32>, cudaFuncAttributeMaxDynamicSharedMemorySize, SM_N256_32);
    cudaFuncSetAttribute(ln_gemm_n32, cudaFuncAttributeMaxDynamicSharedMemorySize, SM_LN32);
    cudaFuncSetAttribute(ln_gemm_n54, cudaFuncAttributeMaxDynamicSharedMemorySize, SM_LN54);

    // ---- encoder: frozen FFMA2 fp32 path (bit-identical z -> indices) ----
    small_gemm_n256<54><<<Bsz / 32, 256, SM_N256_54>>>(x, epw, epb, h);
    for (int i = 0; i < NB; i++) {
        ln_stats<<<Bsz / 8, 256>>>(h, (float2*)stats);
        gemm128<<<dim3(EXPD / 128, Bsz / 128), 256>>>(
            h, ew1 + (size_t)i * HID * EXPD, eb1 + i * EXPD, nullptr, y, HID, EXPD, 1,
            (const float2*)stats, elng + i * HID, elnb + i * HID);
        gemm128<<<dim3(HID / 128, Bsz / 128), 256>>>(
            y, ew2 + (size_t)i * EXPD * HID, eb2 + i * HID, h, h, EXPD, HID, 2,
            nullptr, nullptr, nullptr);
    }
    ln_gemm_n32<<<Bsz / 32, 256, SM_LN32>>>(h, eng, enb, elw, elb, z);

    // ---- VQ (8 rows/warp; indices bit-identical) ----
    vq_kernel<<<Bsz / 64, 256, (NC * LAT + NC) * 4>>>(z, cb, o_idx, o_zq, zq, part);
    loss_reduce<<<1, 1024>>>(part, o_loss);

    // ---- decoder weight prep: single fused launch ----
    tsplit8<<<4096, 256>>>(dw1, dw2, wh16, wl16);

    // ---- decoder: bf16 split mma pipeline ----
    small_gemm_n256<32><<<Bsz / 32, 256, SM_N256_32>>>(zq, dlw, dlb, h);
    for (int i = 0; i < NB; i++) {
        ln_split<<<Bsz / 8, 256>>>(h, dlng + i * HID, dlnb + i * HID, ah16, al16);
        mma2<<<dim3(EXPD / 128, Bsz / 128), 256, MMA_SMEM>>>(
            ah16, al16, wh16 + (size_t)i * 131072, wl16 + (size_t)i * 131072, db1 + i * EXPD,
            nullptr, nullptr, yh16, yl16, HID, EXPD, 1);
        mma2<<<dim3(HID / 128, Bsz / 128), 256, MMA_SMEM>>>(
            yh16, yl16, wh16 + (size_t)(4 + i) * 131072, wl16 + (size_t)(4 + i) * 131072, db2 + i * HID,
            h, h, nullptr, nullptr, EXPD, HID, 2);
    }
    ln_gemm_n54<<<Bsz / 32, 256, SM_LN54>>>(h, dng, dnb, dpw, dpb, o_xrec);
}